// round 1
// baseline (speedup 1.0000x reference)
#include <cuda_runtime.h>

#define Nn 50000
#define Ee 640000
#define Dd 128
#define Rr 8

// Scratch (static device allocations are allowed; cudaMalloc is not)
__device__ float g_hall[(size_t)Rr * Nn * Dd];   // [R, N, O] relation projections
__device__ float g_b1[(size_t)Nn * Dd];          // x@w1 + b, then += scatter
__device__ float g_b2[(size_t)Nn * Dd];          // relu(b1@m1 + b1m)

// C[n_rows,128] = A[n_rows,128] @ B[128,128] (+bias) (relu)
// blockIdx.y batches over B/C (relation GEMMs).
template<bool BIAS, bool RELU>
__global__ __launch_bounds__(256) void gemm_k128(
    const float* __restrict__ A,
    const float* __restrict__ Bg, long long Bstride,
    const float* __restrict__ bias,
    float* __restrict__ Cg, long long Cstride,
    int n_rows)
{
    const float* B = Bg + (size_t)blockIdx.y * Bstride;
    float* C       = Cg + (size_t)blockIdx.y * Cstride;
    const int row0 = blockIdx.x * 128;

    __shared__ __align__(16) float As[16][128];
    __shared__ __align__(16) float Bs[16][128];

    const int tid = threadIdx.x;          // 256 threads
    const int tx  = tid & 15;
    const int ty  = tid >> 4;

    float acc[8][8];
#pragma unroll
    for (int i = 0; i < 8; ++i)
#pragma unroll
        for (int j = 0; j < 8; ++j) acc[i][j] = 0.f;

    // A-tile loader mapping: 2 threads per row, each loads 2 float4 (8 k's)
    const int lrow = tid >> 1;
    const int q    = tid & 1;
    const int grow = row0 + lrow;
    const bool rok = (grow < n_rows);
    const float4* Arow = (const float4*)(A + (size_t)grow * 128) + q * 2;

    for (int k0 = 0; k0 < 128; k0 += 16) {
        float4 v0 = make_float4(0.f, 0.f, 0.f, 0.f), v1 = v0;
        if (rok) { v0 = Arow[0]; v1 = Arow[1]; }
        Arow += 4;  // advance 16 floats

        const int kb = q * 8;
        As[kb + 0][lrow] = v0.x; As[kb + 1][lrow] = v0.y;
        As[kb + 2][lrow] = v0.z; As[kb + 3][lrow] = v0.w;
        As[kb + 4][lrow] = v1.x; As[kb + 5][lrow] = v1.y;
        As[kb + 6][lrow] = v1.z; As[kb + 7][lrow] = v1.w;

        // B tile: straight vectorized copy of rows [k0, k0+16)
        const float4* B4  = (const float4*)(B + (size_t)k0 * 128);
        float4*       Bs4 = (float4*)&Bs[0][0];
        Bs4[tid]       = B4[tid];
        Bs4[tid + 256] = B4[tid + 256];

        __syncthreads();

#pragma unroll
        for (int k = 0; k < 16; ++k) {
            const float4 a0 = *(const float4*)&As[k][ty * 4];
            const float4 a1 = *(const float4*)&As[k][ty * 4 + 64];
            const float4 b0 = *(const float4*)&Bs[k][tx * 4];
            const float4 b1 = *(const float4*)&Bs[k][tx * 4 + 64];
            const float a[8] = {a0.x, a0.y, a0.z, a0.w, a1.x, a1.y, a1.z, a1.w};
            const float b[8] = {b0.x, b0.y, b0.z, b0.w, b1.x, b1.y, b1.z, b1.w};
#pragma unroll
            for (int i = 0; i < 8; ++i)
#pragma unroll
                for (int j = 0; j < 8; ++j)
                    acc[i][j] += a[i] * b[j];
        }
        __syncthreads();
    }

    float bb[8];
    if (BIAS) {
#pragma unroll
        for (int j = 0; j < 8; ++j)
            bb[j] = bias[(j < 4) ? (tx * 4 + j) : (64 + tx * 4 + j - 4)];
    }

#pragma unroll
    for (int i = 0; i < 8; ++i) {
        const int gr = row0 + ((i < 4) ? (ty * 4 + i) : (64 + ty * 4 + i - 4));
        if (gr >= n_rows) continue;
        float o[8];
#pragma unroll
        for (int j = 0; j < 8; ++j) {
            float v = acc[i][j];
            if (BIAS) v += bb[j];
            if (RELU) v = fmaxf(v, 0.f);
            o[j] = v;
        }
        float* Cr = C + (size_t)gr * 128;
        *(float4*)(Cr + tx * 4)      = make_float4(o[0], o[1], o[2], o[3]);
        *(float4*)(Cr + 64 + tx * 4) = make_float4(o[4], o[5], o[6], o[7]);
    }
}

// One warp per edge: gather h_all[etype, src] row (512 B), atomicAdd into agg[dst]
__global__ __launch_bounds__(256) void edge_scatter(
    const float* __restrict__ hall,
    const int* __restrict__ src,
    const int* __restrict__ dst,
    const int* __restrict__ etype,
    float* __restrict__ agg)
{
    const int e    = (blockIdx.x * 256 + threadIdx.x) >> 5;
    const int lane = threadIdx.x & 31;
    if (e >= Ee) return;

    const int s = __ldg(src + e);
    const int d = __ldg(dst + e);
    const int t = __ldg(etype + e);

    const float4 v = ((const float4*)(hall + ((size_t)t * Nn + s) * 128))[lane];
    float* o = agg + (size_t)d * 128 + lane * 4;
    atomicAdd(o + 0, v.x);
    atomicAdd(o + 1, v.y);
    atomicAdd(o + 2, v.z);
    atomicAdd(o + 3, v.w);
}

extern "C" void kernel_launch(void* const* d_in, const int* in_sizes, int n_in,
                              void* d_out, int out_size)
{
    const float* x     = (const float*)d_in[0];
    const int*   src   = (const int*)  d_in[1];
    const int*   dst   = (const int*)  d_in[2];
    const int*   etype = (const int*)  d_in[3];
    const float* W_rel = (const float*)d_in[4];
    const float* w1_W  = (const float*)d_in[5];
    const float* w1_b  = (const float*)d_in[6];
    const float* m1_W  = (const float*)d_in[7];
    const float* m1_b  = (const float*)d_in[8];
    const float* m2_W  = (const float*)d_in[9];
    const float* m2_b  = (const float*)d_in[10];
    float* out = (float*)d_out;

    float *hall, *b1, *b2;
    cudaGetSymbolAddress((void**)&hall, g_hall);
    cudaGetSymbolAddress((void**)&b1,   g_b1);
    cudaGetSymbolAddress((void**)&b2,   g_b2);

    const int rowTiles = (Nn + 127) / 128;  // 391

    // 1) h_all[r] = x @ W_rel[r]   (batched over blockIdx.y)
    gemm_k128<false, false><<<dim3(rowTiles, Rr), 256>>>(
        x, W_rel, (long long)Dd * Dd, nullptr, hall, (long long)Nn * Dd, Nn);

    // 2) b1 = x @ w1_W + w1_b   (scatter adds on top afterwards)
    gemm_k128<true, false><<<rowTiles, 256>>>(
        x, w1_W, 0, w1_b, b1, 0, Nn);

    // 3) b1[dst] += h_all[etype, src]
    edge_scatter<<<Ee / 8, 256>>>(hall, src, dst, etype, b1);

    // 4) b2 = relu(b1 @ m1_W + m1_b)
    gemm_k128<true, true><<<rowTiles, 256>>>(
        b1, m1_W, 0, m1_b, b2, 0, Nn);

    // 5) out = b2 @ m2_W + m2_b
    gemm_k128<true, false><<<rowTiles, 256>>>(
        b2, m2_W, 0, m2_b, out, 0, Nn);
}

// round 2
// speedup vs baseline: 1.4481x; 1.4481x over previous
#include <cuda_runtime.h>
#include <cuda_bf16.h>
#include <cstdint>

#define Nn 50000
#define Ee 640000
#define Dd 128
#define Rr 8

typedef __nv_bfloat16 bf16;

// ---------------- scratch (static device allocations) ----------------
__device__ float g_hall[(size_t)Rr * Nn * Dd];    // [R, N, O] relation projections (fp32)
__device__ float g_b1[(size_t)Nn * Dd];           // x@w1 + b, then += scatter (fp32)
__device__ bf16  g_xhi[(size_t)Nn * Dd];
__device__ bf16  g_xlo[(size_t)Nn * Dd];
__device__ bf16  g_b1hi[(size_t)Nn * Dd];
__device__ bf16  g_b1lo[(size_t)Nn * Dd];
__device__ bf16  g_b2hi[(size_t)Nn * Dd];
__device__ bf16  g_b2lo[(size_t)Nn * Dd];
__device__ bf16  g_Wrhi[(size_t)Rr * Dd * Dd];
__device__ bf16  g_Wrlo[(size_t)Rr * Dd * Dd];
__device__ bf16  g_w1hi[Dd * Dd];
__device__ bf16  g_w1lo[Dd * Dd];
__device__ bf16  g_m1hi[Dd * Dd];
__device__ bf16  g_m1lo[Dd * Dd];
__device__ bf16  g_m2hi[Dd * Dd];
__device__ bf16  g_m2lo[Dd * Dd];

// ---------------- fp32 -> bf16 hi/lo split ----------------
__global__ __launch_bounds__(256) void split_kernel(
    const float4* __restrict__ in, __nv_bfloat162* __restrict__ hi,
    __nv_bfloat162* __restrict__ lo, int n4)
{
    int i = blockIdx.x * 256 + threadIdx.x;
    if (i >= n4) return;
    float4 v = in[i];
    bf16 hx = __float2bfloat16(v.x), hy = __float2bfloat16(v.y);
    bf16 hz = __float2bfloat16(v.z), hw = __float2bfloat16(v.w);
    float rx = v.x - __bfloat162float(hx), ry = v.y - __bfloat162float(hy);
    float rz = v.z - __bfloat162float(hz), rw = v.w - __bfloat162float(hw);
    hi[2 * i + 0] = __nv_bfloat162(hx, hy);
    hi[2 * i + 1] = __nv_bfloat162(hz, hw);
    lo[2 * i + 0] = __nv_bfloat162(__float2bfloat16(rx), __float2bfloat16(ry));
    lo[2 * i + 1] = __nv_bfloat162(__float2bfloat16(rz), __float2bfloat16(rw));
}

// ---------------- tensor-core GEMM, bf16 hi/lo split, K=128, N=128 ----------------
// C[m,128] = A[m,128] @ B[128,128], A = Ahi+Alo, B = Bhi+Blo,
// computed as Ahi*Bhi + Ahi*Blo + Alo*Bhi (fp32 accum).
// Block: 256 thr (8 warps), tile 128x128, warp tile 64x32.
// smem: A chunk 128 rows x 32k bf16 (64B data, 80B stride), B chunk 32k x 128n (256B data, 272B stride).

#define A_STRIDE 80
#define B_STRIDE 272
#define A_BYTES (128 * A_STRIDE)   // 10240
#define B_BYTES (32 * B_STRIDE)    // 8704

__device__ __forceinline__ void cp16(uint32_t dst, const void* src, int sz) {
    asm volatile("cp.async.cg.shared.global [%0], [%1], 16, %2;\n"
                 :: "r"(dst), "l"(src), "r"(sz));
}
__device__ __forceinline__ void cp_commit() { asm volatile("cp.async.commit_group;\n"); }
__device__ __forceinline__ void cp_wait1()  { asm volatile("cp.async.wait_group 1;\n"); }

__device__ __forceinline__ void ldsm4(uint32_t addr, uint32_t& r0, uint32_t& r1,
                                      uint32_t& r2, uint32_t& r3) {
    asm volatile("ldmatrix.sync.aligned.m8n8.x4.shared.b16 {%0,%1,%2,%3}, [%4];"
                 : "=r"(r0), "=r"(r1), "=r"(r2), "=r"(r3) : "r"(addr));
}
__device__ __forceinline__ void ldsm4t(uint32_t addr, uint32_t& r0, uint32_t& r1,
                                       uint32_t& r2, uint32_t& r3) {
    asm volatile("ldmatrix.sync.aligned.m8n8.x4.trans.shared.b16 {%0,%1,%2,%3}, [%4];"
                 : "=r"(r0), "=r"(r1), "=r"(r2), "=r"(r3) : "r"(addr));
}
__device__ __forceinline__ void mma16816(float& d0, float& d1, float& d2, float& d3,
                                         uint32_t a0, uint32_t a1, uint32_t a2, uint32_t a3,
                                         uint32_t b0, uint32_t b1) {
    asm volatile(
        "mma.sync.aligned.m16n8k16.row.col.f32.bf16.bf16.f32 "
        "{%0,%1,%2,%3}, {%4,%5,%6,%7}, {%8,%9}, {%0,%1,%2,%3};"
        : "+f"(d0), "+f"(d1), "+f"(d2), "+f"(d3)
        : "r"(a0), "r"(a1), "r"(a2), "r"(a3), "r"(b0), "r"(b1));
}

template<bool BIAS, bool RELU, bool SPLIT_OUT>
__global__ __launch_bounds__(256) void gemm_tc(
    const bf16* __restrict__ Ahi, const bf16* __restrict__ Alo,
    const bf16* __restrict__ Bhig, const bf16* __restrict__ Blog, long long Bstride,
    const float* __restrict__ bias,
    float* __restrict__ Cfg, long long Cstride,
    bf16* __restrict__ Chi, bf16* __restrict__ Clo,
    int n_rows)
{
    const bf16* Bhi = Bhig + (size_t)blockIdx.y * Bstride;
    const bf16* Blo = Blog + (size_t)blockIdx.y * Bstride;
    float* Cf = Cfg ? (Cfg + (size_t)blockIdx.y * Cstride) : nullptr;
    const int row0 = blockIdx.x * 128;

    __shared__ __align__(16) char sA[2][A_BYTES];
    __shared__ __align__(16) char sB[2][B_BYTES];

    const int tid  = threadIdx.x;
    const int lane = tid & 31;
    const int wid  = tid >> 5;
    const int wm   = wid & 1;    // 2 m-warps x 64 rows
    const int wn   = wid >> 1;   // 4 n-warps x 32 cols

    const uint32_t sA0 = (uint32_t)__cvta_generic_to_shared(&sA[0][0]);
    const uint32_t sB0 = (uint32_t)__cvta_generic_to_shared(&sB[0][0]);

    const bf16* Asegs[3] = {Ahi, Ahi, Alo};
    const bf16* Bsegs[3] = {Bhi, Blo, Bhi};

    float acc[4][4][4];
#pragma unroll
    for (int f = 0; f < 4; ++f)
#pragma unroll
        for (int g = 0; g < 4; ++g)
#pragma unroll
            for (int r = 0; r < 4; ++r) acc[f][g][r] = 0.f;

    // cp.async per-thread mapping (2 chunks each for A and B)
    const int ar0 = tid >> 2,        ac0 = tid & 3;          // + 64 rows for second
    const int br0 = tid >> 4,        bc0 = tid & 15;         // + 16 rows for second

    auto load_stage = [&](int iter, int stage) {
        const int seg = iter >> 2;
        const int kc  = (iter & 3) * 32;
        const bf16* Ag = Asegs[seg];
        const bf16* Bg = Bsegs[seg];
        // A: 128 rows x 32 bf16 = 512 x 16B chunks? no: 128*4 = 512 chunks, 2/thread
        {
            int r = ar0, gr = row0 + r;
            cp16(sA0 + stage * A_BYTES + r * A_STRIDE + ac0 * 16,
                 Ag + (size_t)gr * 128 + kc + ac0 * 8, gr < n_rows ? 16 : 0);
            r = ar0 + 64; gr = row0 + r;
            cp16(sA0 + stage * A_BYTES + r * A_STRIDE + ac0 * 16,
                 Ag + (size_t)gr * 128 + kc + ac0 * 8, gr < n_rows ? 16 : 0);
        }
        // B: 32 rows x 128 bf16 = 32*16 = 512 chunks, 2/thread
        {
            int r = br0;
            cp16(sB0 + stage * B_BYTES + r * B_STRIDE + bc0 * 16,
                 Bg + (size_t)(kc + r) * 128 + bc0 * 8, 16);
            r = br0 + 16;
            cp16(sB0 + stage * B_BYTES + r * B_STRIDE + bc0 * 16,
                 Bg + (size_t)(kc + r) * 128 + bc0 * 8, 16);
        }
    };

    load_stage(0, 0);
    cp_commit();

    const int arow  = lane & 15;
    const int ahalf = lane >> 4;
    const int blrow = lane & 15;
    const int bnc   = (lane >> 4) * 8;

    for (int iter = 0; iter < 12; ++iter) {
        const int cur = iter & 1;
        if (iter + 1 < 12) load_stage(iter + 1, cur ^ 1);
        cp_commit();
        cp_wait1();
        __syncthreads();

        const uint32_t aBase = sA0 + cur * A_BYTES;
        const uint32_t bBase = sB0 + cur * B_BYTES;

#pragma unroll
        for (int s = 0; s < 2; ++s) {
            uint32_t a[4][4];
#pragma unroll
            for (int f = 0; f < 4; ++f) {
                uint32_t addr = aBase + (wm * 64 + f * 16 + arow) * A_STRIDE
                              + (s * 2 + ahalf) * 16;
                ldsm4(addr, a[f][0], a[f][1], a[f][2], a[f][3]);
            }
            uint32_t b[2][4];
#pragma unroll
            for (int g = 0; g < 2; ++g) {
                uint32_t addr = bBase + (s * 16 + blrow) * B_STRIDE
                              + (wn * 32 + g * 16 + bnc) * 2;
                ldsm4t(addr, b[g][0], b[g][1], b[g][2], b[g][3]);
            }
#pragma unroll
            for (int f = 0; f < 4; ++f) {
#pragma unroll
                for (int g = 0; g < 2; ++g) {
                    mma16816(acc[f][g*2+0][0], acc[f][g*2+0][1], acc[f][g*2+0][2], acc[f][g*2+0][3],
                             a[f][0], a[f][1], a[f][2], a[f][3], b[g][0], b[g][1]);
                    mma16816(acc[f][g*2+1][0], acc[f][g*2+1][1], acc[f][g*2+1][2], acc[f][g*2+1][3],
                             a[f][0], a[f][1], a[f][2], a[f][3], b[g][2], b[g][3]);
                }
            }
        }
        __syncthreads();
    }

    // -------- epilogue --------
    const int tr = lane >> 2;          // 0..7
    const int tc = (lane & 3) * 2;     // 0,2,4,6

    float bb[4][2];
    if (BIAS) {
#pragma unroll
        for (int g = 0; g < 4; ++g) {
            int col = wn * 32 + g * 8 + tc;
            bb[g][0] = bias[col];
            bb[g][1] = bias[col + 1];
        }
    }

#pragma unroll
    for (int f = 0; f < 4; ++f) {
        int m0 = row0 + wm * 64 + f * 16 + tr;
        int m1 = m0 + 8;
#pragma unroll
        for (int g = 0; g < 4; ++g) {
            int col = wn * 32 + g * 8 + tc;
            float v00 = acc[f][g][0], v01 = acc[f][g][1];
            float v10 = acc[f][g][2], v11 = acc[f][g][3];
            if (BIAS) { v00 += bb[g][0]; v01 += bb[g][1]; v10 += bb[g][0]; v11 += bb[g][1]; }
            if (RELU) {
                v00 = fmaxf(v00, 0.f); v01 = fmaxf(v01, 0.f);
                v10 = fmaxf(v10, 0.f); v11 = fmaxf(v11, 0.f);
            }
            if (SPLIT_OUT) {
                if (m0 < n_rows) {
                    bf16 h0 = __float2bfloat16(v00), h1 = __float2bfloat16(v01);
                    *(__nv_bfloat162*)(Chi + (size_t)m0 * 128 + col) = __nv_bfloat162(h0, h1);
                    *(__nv_bfloat162*)(Clo + (size_t)m0 * 128 + col) = __nv_bfloat162(
                        __float2bfloat16(v00 - __bfloat162float(h0)),
                        __float2bfloat16(v01 - __bfloat162float(h1)));
                }
                if (m1 < n_rows) {
                    bf16 h0 = __float2bfloat16(v10), h1 = __float2bfloat16(v11);
                    *(__nv_bfloat162*)(Chi + (size_t)m1 * 128 + col) = __nv_bfloat162(h0, h1);
                    *(__nv_bfloat162*)(Clo + (size_t)m1 * 128 + col) = __nv_bfloat162(
                        __float2bfloat16(v10 - __bfloat162float(h0)),
                        __float2bfloat16(v11 - __bfloat162float(h1)));
                }
            } else {
                if (m0 < n_rows) *(float2*)(Cf + (size_t)m0 * 128 + col) = make_float2(v00, v01);
                if (m1 < n_rows) *(float2*)(Cf + (size_t)m1 * 128 + col) = make_float2(v10, v11);
            }
        }
    }
}

// ---------------- edge scatter: one warp per edge ----------------
__global__ __launch_bounds__(256) void edge_scatter(
    const float* __restrict__ hall,
    const int* __restrict__ src,
    const int* __restrict__ dst,
    const int* __restrict__ etype,
    float* __restrict__ agg)
{
    const int e    = (blockIdx.x * 256 + threadIdx.x) >> 5;
    const int lane = threadIdx.x & 31;
    if (e >= Ee) return;

    const int s = __ldg(src + e);
    const int d = __ldg(dst + e);
    const int t = __ldg(etype + e);

    const float4 v = ((const float4*)(hall + ((size_t)t * Nn + s) * 128))[lane];
    float* o = agg + (size_t)d * 128 + lane * 4;
    atomicAdd(o + 0, v.x);
    atomicAdd(o + 1, v.y);
    atomicAdd(o + 2, v.z);
    atomicAdd(o + 3, v.w);
}

// ---------------- launch ----------------
extern "C" void kernel_launch(void* const* d_in, const int* in_sizes, int n_in,
                              void* d_out, int out_size)
{
    const float* x     = (const float*)d_in[0];
    const int*   src   = (const int*)  d_in[1];
    const int*   dst   = (const int*)  d_in[2];
    const int*   etype = (const int*)  d_in[3];
    const float* W_rel = (const float*)d_in[4];
    const float* w1_W  = (const float*)d_in[5];
    const float* w1_b  = (const float*)d_in[6];
    const float* m1_W  = (const float*)d_in[7];
    const float* m1_b  = (const float*)d_in[8];
    const float* m2_W  = (const float*)d_in[9];
    const float* m2_b  = (const float*)d_in[10];
    float* out = (float*)d_out;

    float *hall, *b1;
    bf16 *xhi, *xlo, *b1hi, *b1lo, *b2hi, *b2lo;
    bf16 *Wrhi, *Wrlo, *w1hi, *w1lo, *m1hi, *m1lo, *m2hi, *m2lo;
    cudaGetSymbolAddress((void**)&hall, g_hall);
    cudaGetSymbolAddress((void**)&b1,   g_b1);
    cudaGetSymbolAddress((void**)&xhi,  g_xhi);
    cudaGetSymbolAddress((void**)&xlo,  g_xlo);
    cudaGetSymbolAddress((void**)&b1hi, g_b1hi);
    cudaGetSymbolAddress((void**)&b1lo, g_b1lo);
    cudaGetSymbolAddress((void**)&b2hi, g_b2hi);
    cudaGetSymbolAddress((void**)&b2lo, g_b2lo);
    cudaGetSymbolAddress((void**)&Wrhi, g_Wrhi);
    cudaGetSymbolAddress((void**)&Wrlo, g_Wrlo);
    cudaGetSymbolAddress((void**)&w1hi, g_w1hi);
    cudaGetSymbolAddress((void**)&w1lo, g_w1lo);
    cudaGetSymbolAddress((void**)&m1hi, g_m1hi);
    cudaGetSymbolAddress((void**)&m1lo, g_m1lo);
    cudaGetSymbolAddress((void**)&m2hi, g_m2hi);
    cudaGetSymbolAddress((void**)&m2lo, g_m2lo);

    const int rowTiles = (Nn + 127) / 128;  // 391

    // splits
    {
        int n4 = Nn * Dd / 4;
        split_kernel<<<(n4 + 255) / 256, 256>>>((const float4*)x,
            (__nv_bfloat162*)xhi, (__nv_bfloat162*)xlo, n4);
        n4 = Rr * Dd * Dd / 4;
        split_kernel<<<(n4 + 255) / 256, 256>>>((const float4*)W_rel,
            (__nv_bfloat162*)Wrhi, (__nv_bfloat162*)Wrlo, n4);
        n4 = Dd * Dd / 4;
        split_kernel<<<(n4 + 255) / 256, 256>>>((const float4*)w1_W,
            (__nv_bfloat162*)w1hi, (__nv_bfloat162*)w1lo, n4);
        split_kernel<<<(n4 + 255) / 256, 256>>>((const float4*)m1_W,
            (__nv_bfloat162*)m1hi, (__nv_bfloat162*)m1lo, n4);
        split_kernel<<<(n4 + 255) / 256, 256>>>((const float4*)m2_W,
            (__nv_bfloat162*)m2hi, (__nv_bfloat162*)m2lo, n4);
    }

    // 1) hall[r] = x @ W_rel[r]
    gemm_tc<false, false, false><<<dim3(rowTiles, Rr), 256>>>(
        xhi, xlo, Wrhi, Wrlo, (long long)Dd * Dd, nullptr,
        hall, (long long)Nn * Dd, nullptr, nullptr, Nn);

    // 2) b1 = x @ w1_W + w1_b
    gemm_tc<true, false, false><<<rowTiles, 256>>>(
        xhi, xlo, w1hi, w1lo, 0, w1_b, b1, 0, nullptr, nullptr, Nn);

    // 3) b1[dst] += hall[etype, src]
    edge_scatter<<<Ee / 8, 256>>>(hall, src, dst, etype, b1);

    // 4) split b1
    {
        int n4 = Nn * Dd / 4;
        split_kernel<<<(n4 + 255) / 256, 256>>>((const float4*)b1,
            (__nv_bfloat162*)b1hi, (__nv_bfloat162*)b1lo, n4);
    }

    // 5) b2 = relu(b1 @ m1_W + m1_b), emitted directly as split bf16
    gemm_tc<true, true, true><<<rowTiles, 256>>>(
        b1hi, b1lo, m1hi, m1lo, 0, m1_b, nullptr, 0, b2hi, b2lo, Nn);

    // 6) out = b2 @ m2_W + m2_b
    gemm_tc<true, false, false><<<rowTiles, 256>>>(
        b2hi, b2lo, m2hi, m2lo, 0, m2_b, out, 0, nullptr, nullptr, Nn);
}

// round 4
// speedup vs baseline: 1.5052x; 1.0394x over previous
#include <cuda_runtime.h>
#include <cuda_bf16.h>
#include <cstdint>

#define Nn 50000
#define Ee 640000
#define Rr 8
typedef __nv_bfloat16 bf16;

// ---------------- scratch ----------------
__device__ float g_hall[(size_t)Rr * Nn * 128];
__device__ float g_b1[(size_t)Nn * 128];
__device__ bf16  g_xhi[(size_t)Nn * 128],  g_xlo[(size_t)Nn * 128];
__device__ bf16  g_b1hi[(size_t)Nn * 128], g_b1lo[(size_t)Nn * 128];
__device__ bf16  g_b2hi[(size_t)Nn * 128], g_b2lo[(size_t)Nn * 128];
__device__ bf16  g_Wchi[9 * 128 * 128], g_Wclo[9 * 128 * 128];   // 8 rels + w1
__device__ bf16  g_m1hi[128 * 128], g_m1lo[128 * 128];
__device__ bf16  g_m2hi[128 * 128], g_m2lo[128 * 128];

// ---------------- asm helpers ----------------
__device__ __forceinline__ uint32_t s2u(const void* p) {
    return (uint32_t)__cvta_generic_to_shared(p);
}
__device__ __forceinline__ void cp16z(uint32_t d, const void* s, int sz) {
    asm volatile("cp.async.cg.shared.global [%0],[%1],16,%2;\n" :: "r"(d), "l"(s), "r"(sz));
}
__device__ __forceinline__ void cp_commit() { asm volatile("cp.async.commit_group;\n"); }
template<int N> __device__ __forceinline__ void cp_wait() {
    asm volatile("cp.async.wait_group %0;\n" :: "n"(N));
}
__device__ __forceinline__ void ldsm4(uint32_t a, uint32_t& r0, uint32_t& r1,
                                      uint32_t& r2, uint32_t& r3) {
    asm volatile("ldmatrix.sync.aligned.m8n8.x4.shared.b16 {%0,%1,%2,%3}, [%4];"
                 : "=r"(r0), "=r"(r1), "=r"(r2), "=r"(r3) : "r"(a));
}
__device__ __forceinline__ void ldsm4t(uint32_t a, uint32_t& r0, uint32_t& r1,
                                       uint32_t& r2, uint32_t& r3) {
    asm volatile("ldmatrix.sync.aligned.m8n8.x4.trans.shared.b16 {%0,%1,%2,%3}, [%4];"
                 : "=r"(r0), "=r"(r1), "=r"(r2), "=r"(r3) : "r"(a));
}
__device__ __forceinline__ void mma16816(float& d0, float& d1, float& d2, float& d3,
                                         uint32_t a0, uint32_t a1, uint32_t a2, uint32_t a3,
                                         uint32_t b0, uint32_t b1) {
    asm volatile(
        "mma.sync.aligned.m16n8k16.row.col.f32.bf16.bf16.f32 "
        "{%0,%1,%2,%3}, {%4,%5,%6,%7}, {%8,%9}, {%0,%1,%2,%3};"
        : "+f"(d0), "+f"(d1), "+f"(d2), "+f"(d3)
        : "r"(a0), "r"(a1), "r"(a2), "r"(a3), "r"(b0), "r"(b1));
}

// ================= fused relation GEMM =================
// A (x hi+lo) resident in smem; loop over 9 B matrices (8 rels -> hall, w1 -> b1+bias).
// Block 256 thr (8 warps, 2m x 4n, warp tile 64x32).
#define A_STRIDE 80
#define A_CHUNK  (128 * A_STRIDE)   // 10240
#define A_SEG    (4 * A_CHUNK)      // 40960
#define B_STRIDE 272
#define B_CHUNK  (32 * B_STRIDE)    // 8704
#define B_SEG    (4 * B_CHUNK)      // 34816
#define B_BUF    (2 * B_SEG)        // 69632 (hi+lo)
#define FUSED_SMEM (2 * A_SEG + 2 * B_BUF)   // 221184

__global__ __launch_bounds__(256, 1) void rgemm_fused(
    const bf16* __restrict__ Ahi, const bf16* __restrict__ Alo,
    const bf16* __restrict__ Whi, const bf16* __restrict__ Wlo,  // [9][128][128]
    const float* __restrict__ w1_b,
    float* __restrict__ hall, float* __restrict__ b1, int n_rows)
{
    extern __shared__ __align__(16) char sm[];
    const uint32_t sA0 = s2u(sm);
    const uint32_t sB0 = sA0 + 2 * A_SEG;

    const int tid = threadIdx.x, lane = tid & 31, wid = tid >> 5;
    const int wm = wid & 1, wn = wid >> 1;
    const int row0 = blockIdx.x * 128;

    // ---- load resident A (hi+lo, 4 k32-chunks each) ----
    {
        const int r = tid >> 2;       // 0..63
        const int q = tid & 3;        // 16B sub-col of a 32k (64B) row segment
#pragma unroll
        for (int seg = 0; seg < 2; ++seg) {
            const bf16* g = seg ? Alo : Ahi;
#pragma unroll
            for (int c = 0; c < 4; ++c) {
                int gr = row0 + r;
                cp16z(sA0 + seg * A_SEG + c * A_CHUNK + r * A_STRIDE + q * 16,
                      g + (size_t)gr * 128 + c * 32 + q * 8, gr < n_rows ? 16 : 0);
                gr = row0 + r + 64;
                cp16z(sA0 + seg * A_SEG + c * A_CHUNK + (r + 64) * A_STRIDE + q * 16,
                      g + (size_t)gr * 128 + c * 32 + q * 8, gr < n_rows ? 16 : 0);
            }
        }
    }

    const int br = tid >> 4;   // 0..15
    const int bq = tid & 15;
    auto loadB = [&](int rel, int buf) {
#pragma unroll
        for (int seg = 0; seg < 2; ++seg) {
            const bf16* g = (seg ? Wlo : Whi) + (size_t)rel * 16384;
#pragma unroll
            for (int c = 0; c < 4; ++c) {
                cp16z(sB0 + buf * B_BUF + seg * B_SEG + c * B_CHUNK + br * B_STRIDE + bq * 16,
                      g + (size_t)(c * 32 + br) * 128 + bq * 8, 16);
                cp16z(sB0 + buf * B_BUF + seg * B_SEG + c * B_CHUNK + (br + 16) * B_STRIDE + bq * 16,
                      g + (size_t)(c * 32 + br + 16) * 128 + bq * 8, 16);
            }
        }
    };
    loadB(0, 0);
    cp_commit();

    float acc[4][4][4];
#pragma unroll
    for (int f = 0; f < 4; ++f)
#pragma unroll
        for (int g = 0; g < 4; ++g)
#pragma unroll
            for (int r = 0; r < 4; ++r) acc[f][g][r] = 0.f;

    const int arow  = lane & 15, ahalf = lane >> 4;
    const int blrow = lane & 15, bnc = (lane >> 4) * 8;
    const int tr = lane >> 2, tc = (lane & 3) * 2;

    for (int rel = 0; rel < 9; ++rel) {
        const int buf = rel & 1;
        cp_wait<0>();
        __syncthreads();
        if (rel < 8) { loadB(rel + 1, buf ^ 1); cp_commit(); }

        const uint32_t bB = sB0 + buf * B_BUF;
#pragma unroll
        for (int c = 0; c < 4; ++c) {
#pragma unroll
            for (int s = 0; s < 2; ++s) {
                uint32_t ah[4][4], al[4][4], bh[2][4], bl[2][4];
#pragma unroll
                for (int f = 0; f < 4; ++f) {
                    uint32_t aa = sA0 + c * A_CHUNK + (wm * 64 + f * 16 + arow) * A_STRIDE
                                + (s * 2 + ahalf) * 16;
                    ldsm4(aa,         ah[f][0], ah[f][1], ah[f][2], ah[f][3]);
                    ldsm4(aa + A_SEG, al[f][0], al[f][1], al[f][2], al[f][3]);
                }
#pragma unroll
                for (int g = 0; g < 2; ++g) {
                    uint32_t ba = bB + c * B_CHUNK + (s * 16 + blrow) * B_STRIDE
                                + (wn * 32 + g * 16 + bnc) * 2;
                    ldsm4t(ba,         bh[g][0], bh[g][1], bh[g][2], bh[g][3]);
                    ldsm4t(ba + B_SEG, bl[g][0], bl[g][1], bl[g][2], bl[g][3]);
                }
#pragma unroll
                for (int f = 0; f < 4; ++f) {
#pragma unroll
                    for (int g = 0; g < 2; ++g) {
                        // Ahi*Bhi
                        mma16816(acc[f][g*2+0][0], acc[f][g*2+0][1], acc[f][g*2+0][2], acc[f][g*2+0][3],
                                 ah[f][0], ah[f][1], ah[f][2], ah[f][3], bh[g][0], bh[g][1]);
                        mma16816(acc[f][g*2+1][0], acc[f][g*2+1][1], acc[f][g*2+1][2], acc[f][g*2+1][3],
                                 ah[f][0], ah[f][1], ah[f][2], ah[f][3], bh[g][2], bh[g][3]);
                        // Ahi*Blo
                        mma16816(acc[f][g*2+0][0], acc[f][g*2+0][1], acc[f][g*2+0][2], acc[f][g*2+0][3],
                                 ah[f][0], ah[f][1], ah[f][2], ah[f][3], bl[g][0], bl[g][1]);
                        mma16816(acc[f][g*2+1][0], acc[f][g*2+1][1], acc[f][g*2+1][2], acc[f][g*2+1][3],
                                 ah[f][0], ah[f][1], ah[f][2], ah[f][3], bl[g][2], bl[g][3]);
                        // Alo*Bhi
                        mma16816(acc[f][g*2+0][0], acc[f][g*2+0][1], acc[f][g*2+0][2], acc[f][g*2+0][3],
                                 al[f][0], al[f][1], al[f][2], al[f][3], bh[g][0], bh[g][1]);
                        mma16816(acc[f][g*2+1][0], acc[f][g*2+1][1], acc[f][g*2+1][2], acc[f][g*2+1][3],
                                 al[f][0], al[f][1], al[f][2], al[f][3], bh[g][2], bh[g][3]);
                    }
                }
            }
        }

        // ---- epilogue for this B matrix ----
        float* C = (rel < 8) ? (hall + (size_t)rel * Nn * 128) : b1;
        const bool useBias = (rel == 8);
#pragma unroll
        for (int f = 0; f < 4; ++f) {
            int m0 = row0 + wm * 64 + f * 16 + tr;
            int m1 = m0 + 8;
#pragma unroll
            for (int g = 0; g < 4; ++g) {
                int col = wn * 32 + g * 8 + tc;
                float v00 = acc[f][g][0], v01 = acc[f][g][1];
                float v10 = acc[f][g][2], v11 = acc[f][g][3];
                if (useBias) {
                    float bb0 = w1_b[col], bb1 = w1_b[col + 1];
                    v00 += bb0; v01 += bb1; v10 += bb0; v11 += bb1;
                }
                if (m0 < n_rows) *(float2*)(C + (size_t)m0 * 128 + col) = make_float2(v00, v01);
                if (m1 < n_rows) *(float2*)(C + (size_t)m1 * 128 + col) = make_float2(v10, v11);
                acc[f][g][0] = acc[f][g][1] = acc[f][g][2] = acc[f][g][3] = 0.f;
            }
        }
    }
}

// ================= single-B GEMM (round-2 proven) =================
#define G_A_BYTES (128 * A_STRIDE)
#define G_B_BYTES (32 * B_STRIDE)

template<bool BIAS, bool RELU, bool SPLIT_OUT>
__global__ __launch_bounds__(256) void gemm_tc(
    const bf16* __restrict__ Ahi, const bf16* __restrict__ Alo,
    const bf16* __restrict__ Bhi, const bf16* __restrict__ Blo,
    const float* __restrict__ bias,
    float* __restrict__ Cf, bf16* __restrict__ Chi, bf16* __restrict__ Clo,
    int n_rows)
{
    const int row0 = blockIdx.x * 128;

    __shared__ __align__(16) char sA[2][G_A_BYTES];
    __shared__ __align__(16) char sB[2][G_B_BYTES];

    const int tid = threadIdx.x, lane = tid & 31, wid = tid >> 5;
    const int wm = wid & 1, wn = wid >> 1;

    const uint32_t sA0 = s2u(&sA[0][0]);
    const uint32_t sB0 = s2u(&sB[0][0]);

    const bf16* Asegs[3] = {Ahi, Ahi, Alo};
    const bf16* Bsegs[3] = {Bhi, Blo, Bhi};

    float acc[4][4][4];
#pragma unroll
    for (int f = 0; f < 4; ++f)
#pragma unroll
        for (int g = 0; g < 4; ++g)
#pragma unroll
            for (int r = 0; r < 4; ++r) acc[f][g][r] = 0.f;

    const int ar0 = tid >> 2, ac0 = tid & 3;
    const int br0 = tid >> 4, bc0 = tid & 15;

    auto load_stage = [&](int iter, int stage) {
        const int seg = iter >> 2;
        const int kc  = (iter & 3) * 32;
        const bf16* Ag = Asegs[seg];
        const bf16* Bg = Bsegs[seg];
        int r = ar0, gr = row0 + r;
        cp16z(sA0 + stage * G_A_BYTES + r * A_STRIDE + ac0 * 16,
              Ag + (size_t)gr * 128 + kc + ac0 * 8, gr < n_rows ? 16 : 0);
        r = ar0 + 64; gr = row0 + r;
        cp16z(sA0 + stage * G_A_BYTES + r * A_STRIDE + ac0 * 16,
              Ag + (size_t)gr * 128 + kc + ac0 * 8, gr < n_rows ? 16 : 0);
        r = br0;
        cp16z(sB0 + stage * G_B_BYTES + r * B_STRIDE + bc0 * 16,
              Bg + (size_t)(kc + r) * 128 + bc0 * 8, 16);
        r = br0 + 16;
        cp16z(sB0 + stage * G_B_BYTES + r * B_STRIDE + bc0 * 16,
              Bg + (size_t)(kc + r) * 128 + bc0 * 8, 16);
    };

    load_stage(0, 0);
    cp_commit();

    const int arow = lane & 15, ahalf = lane >> 4;
    const int blrow = lane & 15, bnc = (lane >> 4) * 8;

    for (int iter = 0; iter < 12; ++iter) {
        const int cur = iter & 1;
        if (iter + 1 < 12) load_stage(iter + 1, cur ^ 1);
        cp_commit();
        cp_wait<1>();
        __syncthreads();

        const uint32_t aBase = sA0 + cur * G_A_BYTES;
        const uint32_t bBase = sB0 + cur * G_B_BYTES;

#pragma unroll
        for (int s = 0; s < 2; ++s) {
            uint32_t a[4][4];
#pragma unroll
            for (int f = 0; f < 4; ++f) {
                uint32_t addr = aBase + (wm * 64 + f * 16 + arow) * A_STRIDE + (s * 2 + ahalf) * 16;
                ldsm4(addr, a[f][0], a[f][1], a[f][2], a[f][3]);
            }
            uint32_t b[2][4];
#pragma unroll
            for (int g = 0; g < 2; ++g) {
                uint32_t addr = bBase + (s * 16 + blrow) * B_STRIDE + (wn * 32 + g * 16 + bnc) * 2;
                ldsm4t(addr, b[g][0], b[g][1], b[g][2], b[g][3]);
            }
#pragma unroll
            for (int f = 0; f < 4; ++f)
#pragma unroll
                for (int g = 0; g < 2; ++g) {
                    mma16816(acc[f][g*2+0][0], acc[f][g*2+0][1], acc[f][g*2+0][2], acc[f][g*2+0][3],
                             a[f][0], a[f][1], a[f][2], a[f][3], b[g][0], b[g][1]);
                    mma16816(acc[f][g*2+1][0], acc[f][g*2+1][1], acc[f][g*2+1][2], acc[f][g*2+1][3],
                             a[f][0], a[f][1], a[f][2], a[f][3], b[g][2], b[g][3]);
                }
        }
        __syncthreads();
    }

    const int tr = lane >> 2, tc = (lane & 3) * 2;
#pragma unroll
    for (int f = 0; f < 4; ++f) {
        int m0 = row0 + wm * 64 + f * 16 + tr;
        int m1 = m0 + 8;
#pragma unroll
        for (int g = 0; g < 4; ++g) {
            int col = wn * 32 + g * 8 + tc;
            float v00 = acc[f][g][0], v01 = acc[f][g][1];
            float v10 = acc[f][g][2], v11 = acc[f][g][3];
            if (BIAS) {
                float bb0 = bias[col], bb1 = bias[col + 1];
                v00 += bb0; v01 += bb1; v10 += bb0; v11 += bb1;
            }
            if (RELU) {
                v00 = fmaxf(v00, 0.f); v01 = fmaxf(v01, 0.f);
                v10 = fmaxf(v10, 0.f); v11 = fmaxf(v11, 0.f);
            }
            if (SPLIT_OUT) {
                if (m0 < n_rows) {
                    bf16 h0 = __float2bfloat16(v00), h1 = __float2bfloat16(v01);
                    *(__nv_bfloat162*)(Chi + (size_t)m0 * 128 + col) = __nv_bfloat162(h0, h1);
                    *(__nv_bfloat162*)(Clo + (size_t)m0 * 128 + col) = __nv_bfloat162(
                        __float2bfloat16(v00 - __bfloat162float(h0)),
                        __float2bfloat16(v01 - __bfloat162float(h1)));
                }
                if (m1 < n_rows) {
                    bf16 h0 = __float2bfloat16(v10), h1 = __float2bfloat16(v11);
                    *(__nv_bfloat162*)(Chi + (size_t)m1 * 128 + col) = __nv_bfloat162(h0, h1);
                    *(__nv_bfloat162*)(Clo + (size_t)m1 * 128 + col) = __nv_bfloat162(
                        __float2bfloat16(v10 - __bfloat162float(h0)),
                        __float2bfloat16(v11 - __bfloat162float(h1)));
                }
            } else {
                if (m0 < n_rows) *(float2*)(Cf + (size_t)m0 * 128 + col) = make_float2(v00, v01);
                if (m1 < n_rows) *(float2*)(Cf + (size_t)m1 * 128 + col) = make_float2(v10, v11);
            }
        }
    }
}

// ---------------- fp32 -> bf16 hi/lo split ----------------
__global__ __launch_bounds__(256) void split_kernel(
    const float4* __restrict__ in, __nv_bfloat162* __restrict__ hi,
    __nv_bfloat162* __restrict__ lo, int n4)
{
    int i = blockIdx.x * 256 + threadIdx.x;
    if (i >= n4) return;
    float4 v = in[i];
    bf16 hx = __float2bfloat16(v.x), hy = __float2bfloat16(v.y);
    bf16 hz = __float2bfloat16(v.z), hw = __float2bfloat16(v.w);
    hi[2 * i + 0] = __nv_bfloat162(hx, hy);
    hi[2 * i + 1] = __nv_bfloat162(hz, hw);
    lo[2 * i + 0] = __nv_bfloat162(__float2bfloat16(v.x - __bfloat162float(hx)),
                                   __float2bfloat16(v.y - __bfloat162float(hy)));
    lo[2 * i + 1] = __nv_bfloat162(__float2bfloat16(v.z - __bfloat162float(hz)),
                                   __float2bfloat16(v.w - __bfloat162float(hw)));
}

// ---------------- edge scatter ----------------
__global__ __launch_bounds__(256) void edge_scatter(
    const float* __restrict__ hall,
    const int* __restrict__ src, const int* __restrict__ dst,
    const int* __restrict__ etype, float* __restrict__ agg)
{
    const int e    = (blockIdx.x * 256 + threadIdx.x) >> 5;
    const int lane = threadIdx.x & 31;
    if (e >= Ee) return;
    const int s = __ldg(src + e);
    const int d = __ldg(dst + e);
    const int t = __ldg(etype + e);
    const float4 v = ((const float4*)(hall + ((size_t)t * Nn + s) * 128))[lane];
    float* o = agg + (size_t)d * 128 + lane * 4;
    atomicAdd(o + 0, v.x);
    atomicAdd(o + 1, v.y);
    atomicAdd(o + 2, v.z);
    atomicAdd(o + 3, v.w);
}

// ---------------- launch ----------------
extern "C" void kernel_launch(void* const* d_in, const int* in_sizes, int n_in,
                              void* d_out, int out_size)
{
    const float* x     = (const float*)d_in[0];
    const int*   src   = (const int*)  d_in[1];
    const int*   dst   = (const int*)  d_in[2];
    const int*   etype = (const int*)  d_in[3];
    const float* W_rel = (const float*)d_in[4];
    const float* w1_W  = (const float*)d_in[5];
    const float* w1_b  = (const float*)d_in[6];
    const float* m1_W  = (const float*)d_in[7];
    const float* m1_b  = (const float*)d_in[8];
    const float* m2_W  = (const float*)d_in[9];
    const float* m2_b  = (const float*)d_in[10];
    float* out = (float*)d_out;

    float *hall, *b1;
    bf16 *xhi, *xlo, *b1hi, *b1lo, *b2hi, *b2lo;
    bf16 *Wchi, *Wclo, *m1hi, *m1lo, *m2hi, *m2lo;
    cudaGetSymbolAddress((void**)&hall, g_hall);
    cudaGetSymbolAddress((void**)&b1,   g_b1);
    cudaGetSymbolAddress((void**)&xhi,  g_xhi);
    cudaGetSymbolAddress((void**)&xlo,  g_xlo);
    cudaGetSymbolAddress((void**)&b1hi, g_b1hi);
    cudaGetSymbolAddress((void**)&b1lo, g_b1lo);
    cudaGetSymbolAddress((void**)&b2hi, g_b2hi);
    cudaGetSymbolAddress((void**)&b2lo, g_b2lo);
    cudaGetSymbolAddress((void**)&Wchi, g_Wchi);
    cudaGetSymbolAddress((void**)&Wclo, g_Wclo);
    cudaGetSymbolAddress((void**)&m1hi, g_m1hi);
    cudaGetSymbolAddress((void**)&m1lo, g_m1lo);
    cudaGetSymbolAddress((void**)&m2hi, g_m2hi);
    cudaGetSymbolAddress((void**)&m2lo, g_m2lo);

    cudaFuncSetAttribute(rgemm_fused, cudaFuncAttributeMaxDynamicSharedMemorySize, FUSED_SMEM);

    const int nTiles = (Nn + 127) / 128;  // 391

    // ---- splits ----
    {
        int n4 = Nn * 128 / 4;
        split_kernel<<<(n4 + 255) / 256, 256>>>((const float4*)x,
            (__nv_bfloat162*)xhi, (__nv_bfloat162*)xlo, n4);
        n4 = Rr * 128 * 128 / 4;
        split_kernel<<<(n4 + 255) / 256, 256>>>((const float4*)W_rel,
            (__nv_bfloat162*)Wchi, (__nv_bfloat162*)Wclo, n4);
        n4 = 128 * 128 / 4;
        split_kernel<<<(n4 + 255) / 256, 256>>>((const float4*)w1_W,
            (__nv_bfloat162*)(Wchi + 8 * 16384), (__nv_bfloat162*)(Wclo + 8 * 16384), n4);
        split_kernel<<<(n4 + 255) / 256, 256>>>((const float4*)m1_W,
            (__nv_bfloat162*)m1hi, (__nv_bfloat162*)m1lo, n4);
        split_kernel<<<(n4 + 255) / 256, 256>>>((const float4*)m2_W,
            (__nv_bfloat162*)m2hi, (__nv_bfloat162*)m2lo, n4);
    }

    // ---- 1+2) hall[r] = x @ W_rel[r] (r<8); b1 = x @ w1 + w1_b (rel==8) ----
    rgemm_fused<<<nTiles, 256, FUSED_SMEM>>>(xhi, xlo, Wchi, Wclo, w1_b, hall, b1, Nn);

    // ---- 3) b1[dst] += hall[etype, src] ----
    edge_scatter<<<Ee / 8, 256>>>(hall, src, dst, etype, b1);

    // ---- 4) split b1 ----
    {
        int n4 = Nn * 128 / 4;
        split_kernel<<<(n4 + 255) / 256, 256>>>((const float4*)b1,
            (__nv_bfloat162*)b1hi, (__nv_bfloat162*)b1lo, n4);
    }

    // ---- 5) b2 = relu(b1 @ m1 + m1_b), split out ----
    gemm_tc<true, true, true><<<nTiles, 256>>>(
        b1hi, b1lo, m1hi, m1lo, m1_b, nullptr, b2hi, b2lo, Nn);

    // ---- 6) out = b2 @ m2 + m2_b ----
    gemm_tc<true, false, false><<<nTiles, 256>>>(
        b2hi, b2lo, m2hi, m2lo, m2_b, out, nullptr, nullptr, Nn);
}

// round 6
// speedup vs baseline: 1.9944x; 1.3250x over previous
#include <cuda_runtime.h>
#include <cuda_bf16.h>
#include <cstdint>

#define Nn 50000
#define Ee 640000
#define Rr 8
typedef __nv_bfloat16 bf16;

// ---------------- scratch ----------------
__device__ float g_hall[(size_t)Rr * Nn * 128];
__device__ float g_b1[(size_t)Nn * 128];
__device__ bf16  g_xhi[(size_t)Nn * 128],  g_xlo[(size_t)Nn * 128];
__device__ bf16  g_Wchi[9 * 128 * 128], g_Wclo[9 * 128 * 128];   // 8 rels + w1
__device__ bf16  g_m1hi[128 * 128], g_m1lo[128 * 128];
__device__ bf16  g_m2hi[128 * 128], g_m2lo[128 * 128];

// ---------------- asm helpers ----------------
__device__ __forceinline__ uint32_t s2u(const void* p) {
    return (uint32_t)__cvta_generic_to_shared(p);
}
__device__ __forceinline__ void cp16z(uint32_t d, const void* s, int sz) {
    asm volatile("cp.async.cg.shared.global [%0],[%1],16,%2;\n" :: "r"(d), "l"(s), "r"(sz));
}
__device__ __forceinline__ void cp_commit() { asm volatile("cp.async.commit_group;\n"); }
template<int N> __device__ __forceinline__ void cp_wait() {
    asm volatile("cp.async.wait_group %0;\n" :: "n"(N));
}
__device__ __forceinline__ void ldsm4(uint32_t a, uint32_t& r0, uint32_t& r1,
                                      uint32_t& r2, uint32_t& r3) {
    asm volatile("ldmatrix.sync.aligned.m8n8.x4.shared.b16 {%0,%1,%2,%3}, [%4];"
                 : "=r"(r0), "=r"(r1), "=r"(r2), "=r"(r3) : "r"(a));
}
__device__ __forceinline__ void ldsm4t(uint32_t a, uint32_t& r0, uint32_t& r1,
                                       uint32_t& r2, uint32_t& r3) {
    asm volatile("ldmatrix.sync.aligned.m8n8.x4.trans.shared.b16 {%0,%1,%2,%3}, [%4];"
                 : "=r"(r0), "=r"(r1), "=r"(r2), "=r"(r3) : "r"(a));
}
__device__ __forceinline__ void mma16816(float& d0, float& d1, float& d2, float& d3,
                                         uint32_t a0, uint32_t a1, uint32_t a2, uint32_t a3,
                                         uint32_t b0, uint32_t b1) {
    asm volatile(
        "mma.sync.aligned.m16n8k16.row.col.f32.bf16.bf16.f32 "
        "{%0,%1,%2,%3}, {%4,%5,%6,%7}, {%8,%9}, {%0,%1,%2,%3};"
        : "+f"(d0), "+f"(d1), "+f"(d2), "+f"(d3)
        : "r"(a0), "r"(a1), "r"(a2), "r"(a3), "r"(b0), "r"(b1));
}

#define A_STRIDE 80
#define A_CHUNK  (128 * A_STRIDE)   // 10240
#define A_SEG    (4 * A_CHUNK)      // 40960
#define B_STRIDE 272
#define B_CHUNK  (32 * B_STRIDE)    // 8704
#define B_SEG    (4 * B_CHUNK)      // 34816
#define B_BUF    (2 * B_SEG)        // 69632
#define FUSED_SMEM (2 * A_SEG + 2 * B_BUF)            // 221184
#define MLP_SMEM   (65536 + 2 * A_SEG + 2 * B_SEG)    // 217088

// ================= fused relation GEMM (proven round 4) =================
__global__ __launch_bounds__(256, 1) void rgemm_fused(
    const bf16* __restrict__ Ahi, const bf16* __restrict__ Alo,
    const bf16* __restrict__ Whi, const bf16* __restrict__ Wlo,
    const float* __restrict__ w1_b,
    float* __restrict__ hall, float* __restrict__ b1, int n_rows)
{
    extern __shared__ __align__(16) char sm[];
    const uint32_t sA0 = s2u(sm);
    const uint32_t sB0 = sA0 + 2 * A_SEG;

    const int tid = threadIdx.x, lane = tid & 31, wid = tid >> 5;
    const int wm = wid & 1, wn = wid >> 1;
    const int row0 = blockIdx.x * 128;

    {
        const int r = tid >> 2, q = tid & 3;
#pragma unroll
        for (int seg = 0; seg < 2; ++seg) {
            const bf16* g = seg ? Alo : Ahi;
#pragma unroll
            for (int c = 0; c < 4; ++c) {
                int gr = row0 + r;
                cp16z(sA0 + seg * A_SEG + c * A_CHUNK + r * A_STRIDE + q * 16,
                      g + (size_t)gr * 128 + c * 32 + q * 8, gr < n_rows ? 16 : 0);
                gr = row0 + r + 64;
                cp16z(sA0 + seg * A_SEG + c * A_CHUNK + (r + 64) * A_STRIDE + q * 16,
                      g + (size_t)gr * 128 + c * 32 + q * 8, gr < n_rows ? 16 : 0);
            }
        }
    }

    const int br = tid >> 4, bq = tid & 15;
    auto loadB = [&](int rel, int buf) {
#pragma unroll
        for (int seg = 0; seg < 2; ++seg) {
            const bf16* g = (seg ? Wlo : Whi) + (size_t)rel * 16384;
#pragma unroll
            for (int c = 0; c < 4; ++c) {
                cp16z(sB0 + buf * B_BUF + seg * B_SEG + c * B_CHUNK + br * B_STRIDE + bq * 16,
                      g + (size_t)(c * 32 + br) * 128 + bq * 8, 16);
                cp16z(sB0 + buf * B_BUF + seg * B_SEG + c * B_CHUNK + (br + 16) * B_STRIDE + bq * 16,
                      g + (size_t)(c * 32 + br + 16) * 128 + bq * 8, 16);
            }
        }
    };
    loadB(0, 0);
    cp_commit();

    float acc[4][4][4];
#pragma unroll
    for (int f = 0; f < 4; ++f)
#pragma unroll
        for (int g = 0; g < 4; ++g)
#pragma unroll
            for (int r = 0; r < 4; ++r) acc[f][g][r] = 0.f;

    const int arow = lane & 15, ahalf = lane >> 4;
    const int blrow = lane & 15, bnc = (lane >> 4) * 8;
    const int tr = lane >> 2, tc = (lane & 3) * 2;

    for (int rel = 0; rel < 9; ++rel) {
        const int buf = rel & 1;
        cp_wait<0>();
        __syncthreads();
        if (rel < 8) { loadB(rel + 1, buf ^ 1); cp_commit(); }

        const uint32_t bB = sB0 + buf * B_BUF;
#pragma unroll
        for (int c = 0; c < 4; ++c) {
#pragma unroll
            for (int s = 0; s < 2; ++s) {
                uint32_t ah[4][4], al[4][4], bh[2][4], bl[2][4];
#pragma unroll
                for (int f = 0; f < 4; ++f) {
                    uint32_t aa = sA0 + c * A_CHUNK + (wm * 64 + f * 16 + arow) * A_STRIDE
                                + (s * 2 + ahalf) * 16;
                    ldsm4(aa,         ah[f][0], ah[f][1], ah[f][2], ah[f][3]);
                    ldsm4(aa + A_SEG, al[f][0], al[f][1], al[f][2], al[f][3]);
                }
#pragma unroll
                for (int g = 0; g < 2; ++g) {
                    uint32_t ba = bB + c * B_CHUNK + (s * 16 + blrow) * B_STRIDE
                                + (wn * 32 + g * 16 + bnc) * 2;
                    ldsm4t(ba,         bh[g][0], bh[g][1], bh[g][2], bh[g][3]);
                    ldsm4t(ba + B_SEG, bl[g][0], bl[g][1], bl[g][2], bl[g][3]);
                }
#pragma unroll
                for (int f = 0; f < 4; ++f) {
#pragma unroll
                    for (int g = 0; g < 2; ++g) {
                        mma16816(acc[f][g*2+0][0], acc[f][g*2+0][1], acc[f][g*2+0][2], acc[f][g*2+0][3],
                                 ah[f][0], ah[f][1], ah[f][2], ah[f][3], bh[g][0], bh[g][1]);
                        mma16816(acc[f][g*2+1][0], acc[f][g*2+1][1], acc[f][g*2+1][2], acc[f][g*2+1][3],
                                 ah[f][0], ah[f][1], ah[f][2], ah[f][3], bh[g][2], bh[g][3]);
                        mma16816(acc[f][g*2+0][0], acc[f][g*2+0][1], acc[f][g*2+0][2], acc[f][g*2+0][3],
                                 ah[f][0], ah[f][1], ah[f][2], ah[f][3], bl[g][0], bl[g][1]);
                        mma16816(acc[f][g*2+1][0], acc[f][g*2+1][1], acc[f][g*2+1][2], acc[f][g*2+1][3],
                                 ah[f][0], ah[f][1], ah[f][2], ah[f][3], bl[g][2], bl[g][3]);
                        mma16816(acc[f][g*2+0][0], acc[f][g*2+0][1], acc[f][g*2+0][2], acc[f][g*2+0][3],
                                 al[f][0], al[f][1], al[f][2], al[f][3], bh[g][0], bh[g][1]);
                        mma16816(acc[f][g*2+1][0], acc[f][g*2+1][1], acc[f][g*2+1][2], acc[f][g*2+1][3],
                                 al[f][0], al[f][1], al[f][2], al[f][3], bh[g][2], bh[g][3]);
                    }
                }
            }
        }

        float* C = (rel < 8) ? (hall + (size_t)rel * Nn * 128) : b1;
        const bool useBias = (rel == 8);
#pragma unroll
        for (int f = 0; f < 4; ++f) {
            int m0 = row0 + wm * 64 + f * 16 + tr;
            int m1 = m0 + 8;
#pragma unroll
            for (int g = 0; g < 4; ++g) {
                int col = wn * 32 + g * 8 + tc;
                float v00 = acc[f][g][0], v01 = acc[f][g][1];
                float v10 = acc[f][g][2], v11 = acc[f][g][3];
                if (useBias) {
                    float bb0 = w1_b[col], bb1 = w1_b[col + 1];
                    v00 += bb0; v01 += bb1; v10 += bb0; v11 += bb1;
                }
                if (m0 < n_rows) *(float2*)(C + (size_t)m0 * 128 + col) = make_float2(v00, v01);
                if (m1 < n_rows) *(float2*)(C + (size_t)m1 * 128 + col) = make_float2(v10, v11);
                acc[f][g][0] = acc[f][g][1] = acc[f][g][2] = acc[f][g][3] = 0.f;
            }
        }
    }
}

// ================= fused MLP: out = relu(b1@m1+b)@m2+b, one tile per CTA ========
__global__ __launch_bounds__(256, 1) void mlp_fused(
    const float* __restrict__ B1,
    const bf16* __restrict__ M1hi, const bf16* __restrict__ M1lo,
    const bf16* __restrict__ M2hi, const bf16* __restrict__ M2lo,
    const float* __restrict__ m1_b, const float* __restrict__ m2_b,
    float* __restrict__ out, int n_rows)
{
    extern __shared__ __align__(16) char sm[];
    const uint32_t sStage = s2u(sm);              // 64KB fp32 A tile
    const uint32_t sA0 = sStage + 65536;          // 2 x A_SEG (hi, lo)
    const uint32_t sB0 = sA0 + 2 * A_SEG;         // 2 x B_SEG (hi, lo)

    const int tid = threadIdx.x, lane = tid & 31, wid = tid >> 5;
    const int wm = wid & 1, wn = wid >> 1;
    const int row0 = blockIdx.x * 128;

    // ---- stage fp32 b1 tile (FIXED: full 512B per row, 16 chunks per half-row) ----
    {
        const int r = tid >> 1, h = tid & 1;
        const int gr = row0 + r;
#pragma unroll
        for (int i = 0; i < 16; ++i)
            cp16z(sStage + r * 512 + h * 256 + i * 16,
                  B1 + (size_t)gr * 128 + h * 64 + i * 4, gr < n_rows ? 16 : 0);
    }
    const int br = tid >> 4, bq = tid & 15;
    auto loadB = [&](const bf16* Bh, const bf16* Bl) {
#pragma unroll
        for (int seg = 0; seg < 2; ++seg) {
            const bf16* g = seg ? Bl : Bh;
#pragma unroll
            for (int c = 0; c < 4; ++c) {
                cp16z(sB0 + seg * B_SEG + c * B_CHUNK + br * B_STRIDE + bq * 16,
                      g + (size_t)(c * 32 + br) * 128 + bq * 8, 16);
                cp16z(sB0 + seg * B_SEG + c * B_CHUNK + (br + 16) * B_STRIDE + bq * 16,
                      g + (size_t)(c * 32 + br + 16) * 128 + bq * 8, 16);
            }
        }
    };
    loadB(M1hi, M1lo);
    cp_commit();
    cp_wait<0>();
    __syncthreads();

    // ---- split staged fp32 -> As hi/lo ----
    {
        const int r = tid >> 1, h = tid & 1;
#pragma unroll
        for (int j = 0; j < 32; ++j) {
            int col = h * 64 + j * 2;
            float2 v = *(const float2*)(sm + r * 512 + col * 4);
            bf16 h0 = __float2bfloat16(v.x), h1 = __float2bfloat16(v.y);
            uint32_t off = (col >> 5) * A_CHUNK + r * A_STRIDE + (col & 31) * 2;
            *(__nv_bfloat162*)(sm + 65536 + off) = __nv_bfloat162(h0, h1);
            *(__nv_bfloat162*)(sm + 65536 + A_SEG + off) = __nv_bfloat162(
                __float2bfloat16(v.x - __bfloat162float(h0)),
                __float2bfloat16(v.y - __bfloat162float(h1)));
        }
    }
    __syncthreads();

    float acc[4][4][4];
#pragma unroll
    for (int f = 0; f < 4; ++f)
#pragma unroll
        for (int g = 0; g < 4; ++g)
#pragma unroll
            for (int r = 0; r < 4; ++r) acc[f][g][r] = 0.f;

    const int arow = lane & 15, ahalf = lane >> 4;
    const int blrow = lane & 15, bnc = (lane >> 4) * 8;
    const int tr = lane >> 2, tc = (lane & 3) * 2;

    auto mma_pass = [&]() {
#pragma unroll
        for (int c = 0; c < 4; ++c) {
#pragma unroll
            for (int s = 0; s < 2; ++s) {
                uint32_t ah[4][4], al[4][4], bh[2][4], bl[2][4];
#pragma unroll
                for (int f = 0; f < 4; ++f) {
                    uint32_t aa = sA0 + c * A_CHUNK + (wm * 64 + f * 16 + arow) * A_STRIDE
                                + (s * 2 + ahalf) * 16;
                    ldsm4(aa,         ah[f][0], ah[f][1], ah[f][2], ah[f][3]);
                    ldsm4(aa + A_SEG, al[f][0], al[f][1], al[f][2], al[f][3]);
                }
#pragma unroll
                for (int g = 0; g < 2; ++g) {
                    uint32_t ba = sB0 + c * B_CHUNK + (s * 16 + blrow) * B_STRIDE
                                + (wn * 32 + g * 16 + bnc) * 2;
                    ldsm4t(ba,         bh[g][0], bh[g][1], bh[g][2], bh[g][3]);
                    ldsm4t(ba + B_SEG, bl[g][0], bl[g][1], bl[g][2], bl[g][3]);
                }
#pragma unroll
                for (int f = 0; f < 4; ++f) {
#pragma unroll
                    for (int g = 0; g < 2; ++g) {
                        mma16816(acc[f][g*2+0][0], acc[f][g*2+0][1], acc[f][g*2+0][2], acc[f][g*2+0][3],
                                 ah[f][0], ah[f][1], ah[f][2], ah[f][3], bh[g][0], bh[g][1]);
                        mma16816(acc[f][g*2+1][0], acc[f][g*2+1][1], acc[f][g*2+1][2], acc[f][g*2+1][3],
                                 ah[f][0], ah[f][1], ah[f][2], ah[f][3], bh[g][2], bh[g][3]);
                        mma16816(acc[f][g*2+0][0], acc[f][g*2+0][1], acc[f][g*2+0][2], acc[f][g*2+0][3],
                                 ah[f][0], ah[f][1], ah[f][2], ah[f][3], bl[g][0], bl[g][1]);
                        mma16816(acc[f][g*2+1][0], acc[f][g*2+1][1], acc[f][g*2+1][2], acc[f][g*2+1][3],
                                 ah[f][0], ah[f][1], ah[f][2], ah[f][3], bl[g][2], bl[g][3]);
                        mma16816(acc[f][g*2+0][0], acc[f][g*2+0][1], acc[f][g*2+0][2], acc[f][g*2+0][3],
                                 al[f][0], al[f][1], al[f][2], al[f][3], bh[g][0], bh[g][1]);
                        mma16816(acc[f][g*2+1][0], acc[f][g*2+1][1], acc[f][g*2+1][2], acc[f][g*2+1][3],
                                 al[f][0], al[f][1], al[f][2], al[f][3], bh[g][2], bh[g][3]);
                    }
                }
            }
        }
    };

    // ---- GEMM 1: b1 @ m1 ----
    mma_pass();
    __syncthreads();

    // prefetch m2 weights into Bs
    loadB(M2hi, M2lo);
    cp_commit();

    // bias + relu + split acc -> As (b2 tile, hi/lo)
#pragma unroll
    for (int f = 0; f < 4; ++f) {
        int r0l = wm * 64 + f * 16 + tr;
        int r1l = r0l + 8;
#pragma unroll
        for (int g = 0; g < 4; ++g) {
            int col = wn * 32 + g * 8 + tc;
            float bb0 = m1_b[col], bb1 = m1_b[col + 1];
            float v00 = fmaxf(acc[f][g][0] + bb0, 0.f);
            float v01 = fmaxf(acc[f][g][1] + bb1, 0.f);
            float v10 = fmaxf(acc[f][g][2] + bb0, 0.f);
            float v11 = fmaxf(acc[f][g][3] + bb1, 0.f);
            uint32_t off0 = (col >> 5) * A_CHUNK + r0l * A_STRIDE + (col & 31) * 2;
            uint32_t off1 = (col >> 5) * A_CHUNK + r1l * A_STRIDE + (col & 31) * 2;
            bf16 h00 = __float2bfloat16(v00), h01 = __float2bfloat16(v01);
            bf16 h10 = __float2bfloat16(v10), h11 = __float2bfloat16(v11);
            *(__nv_bfloat162*)(sm + 65536 + off0) = __nv_bfloat162(h00, h01);
            *(__nv_bfloat162*)(sm + 65536 + off1) = __nv_bfloat162(h10, h11);
            *(__nv_bfloat162*)(sm + 65536 + A_SEG + off0) = __nv_bfloat162(
                __float2bfloat16(v00 - __bfloat162float(h00)),
                __float2bfloat16(v01 - __bfloat162float(h01)));
            *(__nv_bfloat162*)(sm + 65536 + A_SEG + off1) = __nv_bfloat162(
                __float2bfloat16(v10 - __bfloat162float(h10)),
                __float2bfloat16(v11 - __bfloat162float(h11)));
            acc[f][g][0] = acc[f][g][1] = acc[f][g][2] = acc[f][g][3] = 0.f;
        }
    }
    cp_wait<0>();
    __syncthreads();

    // ---- GEMM 2: b2 @ m2 ----
    mma_pass();

    // ---- final epilogue ----
#pragma unroll
    for (int f = 0; f < 4; ++f) {
        int m0 = row0 + wm * 64 + f * 16 + tr;
        int m1 = m0 + 8;
#pragma unroll
        for (int g = 0; g < 4; ++g) {
            int col = wn * 32 + g * 8 + tc;
            float bb0 = m2_b[col], bb1 = m2_b[col + 1];
            if (m0 < n_rows)
                *(float2*)(out + (size_t)m0 * 128 + col) =
                    make_float2(acc[f][g][0] + bb0, acc[f][g][1] + bb1);
            if (m1 < n_rows)
                *(float2*)(out + (size_t)m1 * 128 + col) =
                    make_float2(acc[f][g][2] + bb0, acc[f][g][3] + bb1);
        }
    }
}

// ---------------- fp32 -> bf16 hi/lo split (x only) ----------------
__global__ __launch_bounds__(256) void split_kernel(
    const float4* __restrict__ in, __nv_bfloat162* __restrict__ hi,
    __nv_bfloat162* __restrict__ lo, int n4)
{
    int i = blockIdx.x * 256 + threadIdx.x;
    if (i >= n4) return;
    float4 v = in[i];
    bf16 hx = __float2bfloat16(v.x), hy = __float2bfloat16(v.y);
    bf16 hz = __float2bfloat16(v.z), hw = __float2bfloat16(v.w);
    hi[2 * i + 0] = __nv_bfloat162(hx, hy);
    hi[2 * i + 1] = __nv_bfloat162(hz, hw);
    lo[2 * i + 0] = __nv_bfloat162(__float2bfloat16(v.x - __bfloat162float(hx)),
                                   __float2bfloat16(v.y - __bfloat162float(hy)));
    lo[2 * i + 1] = __nv_bfloat162(__float2bfloat16(v.z - __bfloat162float(hz)),
                                   __float2bfloat16(v.w - __bfloat162float(hw)));
}

// ---------------- merged weight split ----------------
__global__ __launch_bounds__(256) void wsplit_kernel(
    const float4* __restrict__ Wrel, const float4* __restrict__ w1W,
    const float4* __restrict__ m1W,  const float4* __restrict__ m2W,
    __nv_bfloat162* __restrict__ Wchi, __nv_bfloat162* __restrict__ Wclo,
    __nv_bfloat162* __restrict__ m1hi, __nv_bfloat162* __restrict__ m1lo,
    __nv_bfloat162* __restrict__ m2hi, __nv_bfloat162* __restrict__ m2lo)
{
    int i = blockIdx.x * 256 + threadIdx.x;
    if (i >= 11 * 4096) return;
    const int mat = i >> 12, local = i & 4095;
    const float4* in;
    __nv_bfloat162 *hi, *lo;
    if (mat < 8)       { in = Wrel + i;    hi = Wchi + i * 2;                  lo = Wclo + i * 2; }
    else if (mat == 8) { in = w1W + local; hi = Wchi + (8 * 4096 + local) * 2; lo = Wclo + (8 * 4096 + local) * 2; }
    else if (mat == 9) { in = m1W + local; hi = m1hi + local * 2;              lo = m1lo + local * 2; }
    else               { in = m2W + local; hi = m2hi + local * 2;              lo = m2lo + local * 2; }
    float4 v = *in;
    bf16 hx = __float2bfloat16(v.x), hy = __float2bfloat16(v.y);
    bf16 hz = __float2bfloat16(v.z), hw = __float2bfloat16(v.w);
    hi[0] = __nv_bfloat162(hx, hy);
    hi[1] = __nv_bfloat162(hz, hw);
    lo[0] = __nv_bfloat162(__float2bfloat16(v.x - __bfloat162float(hx)),
                           __float2bfloat16(v.y - __bfloat162float(hy)));
    lo[1] = __nv_bfloat162(__float2bfloat16(v.z - __bfloat162float(hz)),
                           __float2bfloat16(v.w - __bfloat162float(hw)));
}

// ---------------- edge scatter with vector reductions ----------------
__global__ __launch_bounds__(256) void edge_scatter(
    const float* __restrict__ hall,
    const int* __restrict__ src, const int* __restrict__ dst,
    const int* __restrict__ etype, float* __restrict__ agg)
{
    const int e    = (blockIdx.x * 256 + threadIdx.x) >> 5;
    const int lane = threadIdx.x & 31;
    if (e >= Ee) return;
    const int s = __ldg(src + e);
    const int d = __ldg(dst + e);
    const int t = __ldg(etype + e);
    const float4 v = ((const float4*)(hall + ((size_t)t * Nn + s) * 128))[lane];
    float* o = agg + (size_t)d * 128 + lane * 4;
    asm volatile("red.global.add.v4.f32 [%0], {%1,%2,%3,%4};"
                 :: "l"(o), "f"(v.x), "f"(v.y), "f"(v.z), "f"(v.w) : "memory");
}

// ---------------- launch ----------------
extern "C" void kernel_launch(void* const* d_in, const int* in_sizes, int n_in,
                              void* d_out, int out_size)
{
    const float* x     = (const float*)d_in[0];
    const int*   src   = (const int*)  d_in[1];
    const int*   dst   = (const int*)  d_in[2];
    const int*   etype = (const int*)  d_in[3];
    const float* W_rel = (const float*)d_in[4];
    const float* w1_W  = (const float*)d_in[5];
    const float* w1_b  = (const float*)d_in[6];
    const float* m1_W  = (const float*)d_in[7];
    const float* m1_b  = (const float*)d_in[8];
    const float* m2_W  = (const float*)d_in[9];
    const float* m2_b  = (const float*)d_in[10];
    float* out = (float*)d_out;

    float *hall, *b1;
    bf16 *xhi, *xlo, *Wchi, *Wclo, *m1hi, *m1lo, *m2hi, *m2lo;
    cudaGetSymbolAddress((void**)&hall, g_hall);
    cudaGetSymbolAddress((void**)&b1,   g_b1);
    cudaGetSymbolAddress((void**)&xhi,  g_xhi);
    cudaGetSymbolAddress((void**)&xlo,  g_xlo);
    cudaGetSymbolAddress((void**)&Wchi, g_Wchi);
    cudaGetSymbolAddress((void**)&Wclo, g_Wclo);
    cudaGetSymbolAddress((void**)&m1hi, g_m1hi);
    cudaGetSymbolAddress((void**)&m1lo, g_m1lo);
    cudaGetSymbolAddress((void**)&m2hi, g_m2hi);
    cudaGetSymbolAddress((void**)&m2lo, g_m2lo);

    cudaFuncSetAttribute(rgemm_fused, cudaFuncAttributeMaxDynamicSharedMemorySize, FUSED_SMEM);
    cudaFuncSetAttribute(mlp_fused,   cudaFuncAttributeMaxDynamicSharedMemorySize, MLP_SMEM);

    const int nTiles = (Nn + 127) / 128;  // 391

    {
        int n4 = Nn * 128 / 4;
        split_kernel<<<(n4 + 255) / 256, 256>>>((const float4*)x,
            (__nv_bfloat162*)xhi, (__nv_bfloat162*)xlo, n4);
        wsplit_kernel<<<(11 * 4096 + 255) / 256, 256>>>(
            (const float4*)W_rel, (const float4*)w1_W,
            (const float4*)m1_W, (const float4*)m2_W,
            (__nv_bfloat162*)Wchi, (__nv_bfloat162*)Wclo,
            (__nv_bfloat162*)m1hi, (__nv_bfloat162*)m1lo,
            (__nv_bfloat162*)m2hi, (__nv_bfloat162*)m2lo);
    }

    rgemm_fused<<<nTiles, 256, FUSED_SMEM>>>(xhi, xlo, Wchi, Wclo, w1_b, hall, b1, Nn);

    edge_scatter<<<Ee / 8, 256>>>(hall, src, dst, etype, b1);

    mlp_fused<<<nTiles, 256, MLP_SMEM>>>(b1, m1hi, m1lo, m2hi, m2lo,
                                         m1_b, m2_b, out, Nn);
}

// round 7
// speedup vs baseline: 2.1086x; 1.0573x over previous
#include <cuda_runtime.h>
#include <cuda_bf16.h>
#include <cstdint>

#define Nn 50000
#define Ee 640000
#define Rr 8
typedef __nv_bfloat16 bf16;

// ---------------- scratch ----------------
__device__ float g_hall[(size_t)Rr * Nn * 128];
__device__ float g_b1[(size_t)Nn * 128];
__device__ bf16  g_Wchi[9 * 128 * 128], g_Wclo[9 * 128 * 128];   // 8 rels + w1
__device__ bf16  g_m1hi[128 * 128], g_m1lo[128 * 128];
__device__ bf16  g_m2hi[128 * 128], g_m2lo[128 * 128];

// ---------------- asm helpers ----------------
__device__ __forceinline__ uint32_t s2u(const void* p) {
    return (uint32_t)__cvta_generic_to_shared(p);
}
__device__ __forceinline__ void cp16z(uint32_t d, const void* s, int sz) {
    asm volatile("cp.async.cg.shared.global [%0],[%1],16,%2;\n" :: "r"(d), "l"(s), "r"(sz));
}
__device__ __forceinline__ void cp_commit() { asm volatile("cp.async.commit_group;\n"); }
template<int N> __device__ __forceinline__ void cp_wait() {
    asm volatile("cp.async.wait_group %0;\n" :: "n"(N));
}
__device__ __forceinline__ void ldsm4(uint32_t a, uint32_t& r0, uint32_t& r1,
                                      uint32_t& r2, uint32_t& r3) {
    asm volatile("ldmatrix.sync.aligned.m8n8.x4.shared.b16 {%0,%1,%2,%3}, [%4];"
                 : "=r"(r0), "=r"(r1), "=r"(r2), "=r"(r3) : "r"(a));
}
__device__ __forceinline__ void ldsm4t(uint32_t a, uint32_t& r0, uint32_t& r1,
                                       uint32_t& r2, uint32_t& r3) {
    asm volatile("ldmatrix.sync.aligned.m8n8.x4.trans.shared.b16 {%0,%1,%2,%3}, [%4];"
                 : "=r"(r0), "=r"(r1), "=r"(r2), "=r"(r3) : "r"(a));
}
__device__ __forceinline__ void mma16816(float& d0, float& d1, float& d2, float& d3,
                                         uint32_t a0, uint32_t a1, uint32_t a2, uint32_t a3,
                                         uint32_t b0, uint32_t b1) {
    asm volatile(
        "mma.sync.aligned.m16n8k16.row.col.f32.bf16.bf16.f32 "
        "{%0,%1,%2,%3}, {%4,%5,%6,%7}, {%8,%9}, {%0,%1,%2,%3};"
        : "+f"(d0), "+f"(d1), "+f"(d2), "+f"(d3)
        : "r"(a0), "r"(a1), "r"(a2), "r"(a3), "r"(b0), "r"(b1));
}

#define A_STRIDE 80
#define A_CHUNK  (128 * A_STRIDE)   // 10240
#define A_SEG    (4 * A_CHUNK)      // 40960
#define B_STRIDE 272
#define B_CHUNK  (32 * B_STRIDE)    // 8704
#define B_SEG    (4 * B_CHUNK)      // 34816
#define B_BUF    (2 * B_SEG)        // 69632
#define FUSED_SMEM (2 * A_SEG + 2 * B_BUF)            // 221184
#define MLP_SMEM   (65536 + 2 * A_SEG + 2 * B_SEG)    // 217088

// ================= fused relation GEMM (fp32 x staged + split in-kernel) ========
__global__ __launch_bounds__(256, 1) void rgemm_fused(
    const float* __restrict__ X,
    const bf16* __restrict__ Whi, const bf16* __restrict__ Wlo,
    const float* __restrict__ w1_b,
    float* __restrict__ hall, float* __restrict__ b1, int n_rows)
{
    extern __shared__ __align__(16) char sm[];
    const uint32_t sA0 = s2u(sm);
    const uint32_t sB0 = sA0 + 2 * A_SEG;

    const int tid = threadIdx.x, lane = tid & 31, wid = tid >> 5;
    const int wm = wid & 1, wn = wid >> 1;
    const int row0 = blockIdx.x * 128;

    // ---- stage fp32 x tile into sB area (temporarily free), then split to sA ----
    {
        const int r = tid >> 1, h = tid & 1;
        const int gr = row0 + r;
#pragma unroll
        for (int i = 0; i < 16; ++i)
            cp16z(sB0 + r * 512 + h * 256 + i * 16,
                  X + (size_t)gr * 128 + h * 64 + i * 4, gr < n_rows ? 16 : 0);
        cp_commit();
        cp_wait<0>();
        __syncthreads();
#pragma unroll
        for (int j = 0; j < 32; ++j) {
            int col = h * 64 + j * 2;
            float2 v = *(const float2*)(sm + 2 * A_SEG + r * 512 + col * 4);
            bf16 h0 = __float2bfloat16(v.x), h1 = __float2bfloat16(v.y);
            uint32_t off = (col >> 5) * A_CHUNK + r * A_STRIDE + (col & 31) * 2;
            *(__nv_bfloat162*)(sm + off) = __nv_bfloat162(h0, h1);
            *(__nv_bfloat162*)(sm + A_SEG + off) = __nv_bfloat162(
                __float2bfloat16(v.x - __bfloat162float(h0)),
                __float2bfloat16(v.y - __bfloat162float(h1)));
        }
        __syncthreads();
    }

    const int br = tid >> 4, bq = tid & 15;
    auto loadB = [&](int rel, int buf) {
#pragma unroll
        for (int seg = 0; seg < 2; ++seg) {
            const bf16* g = (seg ? Wlo : Whi) + (size_t)rel * 16384;
#pragma unroll
            for (int c = 0; c < 4; ++c) {
                cp16z(sB0 + buf * B_BUF + seg * B_SEG + c * B_CHUNK + br * B_STRIDE + bq * 16,
                      g + (size_t)(c * 32 + br) * 128 + bq * 8, 16);
                cp16z(sB0 + buf * B_BUF + seg * B_SEG + c * B_CHUNK + (br + 16) * B_STRIDE + bq * 16,
                      g + (size_t)(c * 32 + br + 16) * 128 + bq * 8, 16);
            }
        }
    };
    loadB(0, 0);
    cp_commit();

    float acc[4][4][4];
#pragma unroll
    for (int f = 0; f < 4; ++f)
#pragma unroll
        for (int g = 0; g < 4; ++g)
#pragma unroll
            for (int r = 0; r < 4; ++r) acc[f][g][r] = 0.f;

    const int arow = lane & 15, ahalf = lane >> 4;
    const int blrow = lane & 15, bnc = (lane >> 4) * 8;
    const int tr = lane >> 2, tc = (lane & 3) * 2;

    for (int rel = 0; rel < 9; ++rel) {
        const int buf = rel & 1;
        cp_wait<0>();
        __syncthreads();
        if (rel < 8) { loadB(rel + 1, buf ^ 1); cp_commit(); }

        const uint32_t bB = sB0 + buf * B_BUF;
#pragma unroll
        for (int c = 0; c < 4; ++c) {
#pragma unroll
            for (int s = 0; s < 2; ++s) {
                uint32_t ah[4][4], al[4][4], bh[2][4], bl[2][4];
#pragma unroll
                for (int f = 0; f < 4; ++f) {
                    uint32_t aa = sA0 + c * A_CHUNK + (wm * 64 + f * 16 + arow) * A_STRIDE
                                + (s * 2 + ahalf) * 16;
                    ldsm4(aa,         ah[f][0], ah[f][1], ah[f][2], ah[f][3]);
                    ldsm4(aa + A_SEG, al[f][0], al[f][1], al[f][2], al[f][3]);
                }
#pragma unroll
                for (int g = 0; g < 2; ++g) {
                    uint32_t ba = bB + c * B_CHUNK + (s * 16 + blrow) * B_STRIDE
                                + (wn * 32 + g * 16 + bnc) * 2;
                    ldsm4t(ba,         bh[g][0], bh[g][1], bh[g][2], bh[g][3]);
                    ldsm4t(ba + B_SEG, bl[g][0], bl[g][1], bl[g][2], bl[g][3]);
                }
#pragma unroll
                for (int f = 0; f < 4; ++f) {
#pragma unroll
                    for (int g = 0; g < 2; ++g) {
                        mma16816(acc[f][g*2+0][0], acc[f][g*2+0][1], acc[f][g*2+0][2], acc[f][g*2+0][3],
                                 ah[f][0], ah[f][1], ah[f][2], ah[f][3], bh[g][0], bh[g][1]);
                        mma16816(acc[f][g*2+1][0], acc[f][g*2+1][1], acc[f][g*2+1][2], acc[f][g*2+1][3],
                                 ah[f][0], ah[f][1], ah[f][2], ah[f][3], bh[g][2], bh[g][3]);
                        mma16816(acc[f][g*2+0][0], acc[f][g*2+0][1], acc[f][g*2+0][2], acc[f][g*2+0][3],
                                 ah[f][0], ah[f][1], ah[f][2], ah[f][3], bl[g][0], bl[g][1]);
                        mma16816(acc[f][g*2+1][0], acc[f][g*2+1][1], acc[f][g*2+1][2], acc[f][g*2+1][3],
                                 ah[f][0], ah[f][1], ah[f][2], ah[f][3], bl[g][2], bl[g][3]);
                        mma16816(acc[f][g*2+0][0], acc[f][g*2+0][1], acc[f][g*2+0][2], acc[f][g*2+0][3],
                                 al[f][0], al[f][1], al[f][2], al[f][3], bh[g][0], bh[g][1]);
                        mma16816(acc[f][g*2+1][0], acc[f][g*2+1][1], acc[f][g*2+1][2], acc[f][g*2+1][3],
                                 al[f][0], al[f][1], al[f][2], al[f][3], bh[g][2], bh[g][3]);
                    }
                }
            }
        }

        float* C = (rel < 8) ? (hall + (size_t)rel * Nn * 128) : b1;
        const bool useBias = (rel == 8);
#pragma unroll
        for (int f = 0; f < 4; ++f) {
            int m0 = row0 + wm * 64 + f * 16 + tr;
            int m1 = m0 + 8;
#pragma unroll
            for (int g = 0; g < 4; ++g) {
                int col = wn * 32 + g * 8 + tc;
                float v00 = acc[f][g][0], v01 = acc[f][g][1];
                float v10 = acc[f][g][2], v11 = acc[f][g][3];
                if (useBias) {
                    float bb0 = w1_b[col], bb1 = w1_b[col + 1];
                    v00 += bb0; v01 += bb1; v10 += bb0; v11 += bb1;
                }
                if (m0 < n_rows) *(float2*)(C + (size_t)m0 * 128 + col) = make_float2(v00, v01);
                if (m1 < n_rows) *(float2*)(C + (size_t)m1 * 128 + col) = make_float2(v10, v11);
                acc[f][g][0] = acc[f][g][1] = acc[f][g][2] = acc[f][g][3] = 0.f;
            }
        }
    }
}

// ================= fused MLP (proven round 6) =================
__global__ __launch_bounds__(256, 1) void mlp_fused(
    const float* __restrict__ B1,
    const bf16* __restrict__ M1hi, const bf16* __restrict__ M1lo,
    const bf16* __restrict__ M2hi, const bf16* __restrict__ M2lo,
    const float* __restrict__ m1_b, const float* __restrict__ m2_b,
    float* __restrict__ out, int n_rows)
{
    extern __shared__ __align__(16) char sm[];
    const uint32_t sStage = s2u(sm);
    const uint32_t sA0 = sStage + 65536;
    const uint32_t sB0 = sA0 + 2 * A_SEG;

    const int tid = threadIdx.x, lane = tid & 31, wid = tid >> 5;
    const int wm = wid & 1, wn = wid >> 1;
    const int row0 = blockIdx.x * 128;

    {
        const int r = tid >> 1, h = tid & 1;
        const int gr = row0 + r;
#pragma unroll
        for (int i = 0; i < 16; ++i)
            cp16z(sStage + r * 512 + h * 256 + i * 16,
                  B1 + (size_t)gr * 128 + h * 64 + i * 4, gr < n_rows ? 16 : 0);
    }
    const int br = tid >> 4, bq = tid & 15;
    auto loadB = [&](const bf16* Bh, const bf16* Bl) {
#pragma unroll
        for (int seg = 0; seg < 2; ++seg) {
            const bf16* g = seg ? Bl : Bh;
#pragma unroll
            for (int c = 0; c < 4; ++c) {
                cp16z(sB0 + seg * B_SEG + c * B_CHUNK + br * B_STRIDE + bq * 16,
                      g + (size_t)(c * 32 + br) * 128 + bq * 8, 16);
                cp16z(sB0 + seg * B_SEG + c * B_CHUNK + (br + 16) * B_STRIDE + bq * 16,
                      g + (size_t)(c * 32 + br + 16) * 128 + bq * 8, 16);
            }
        }
    };
    loadB(M1hi, M1lo);
    cp_commit();
    cp_wait<0>();
    __syncthreads();

    {
        const int r = tid >> 1, h = tid & 1;
#pragma unroll
        for (int j = 0; j < 32; ++j) {
            int col = h * 64 + j * 2;
            float2 v = *(const float2*)(sm + r * 512 + col * 4);
            bf16 h0 = __float2bfloat16(v.x), h1 = __float2bfloat16(v.y);
            uint32_t off = (col >> 5) * A_CHUNK + r * A_STRIDE + (col & 31) * 2;
            *(__nv_bfloat162*)(sm + 65536 + off) = __nv_bfloat162(h0, h1);
            *(__nv_bfloat162*)(sm + 65536 + A_SEG + off) = __nv_bfloat162(
                __float2bfloat16(v.x - __bfloat162float(h0)),
                __float2bfloat16(v.y - __bfloat162float(h1)));
        }
    }
    __syncthreads();

    float acc[4][4][4];
#pragma unroll
    for (int f = 0; f < 4; ++f)
#pragma unroll
        for (int g = 0; g < 4; ++g)
#pragma unroll
            for (int r = 0; r < 4; ++r) acc[f][g][r] = 0.f;

    const int arow = lane & 15, ahalf = lane >> 4;
    const int blrow = lane & 15, bnc = (lane >> 4) * 8;
    const int tr = lane >> 2, tc = (lane & 3) * 2;

    auto mma_pass = [&]() {
#pragma unroll
        for (int c = 0; c < 4; ++c) {
#pragma unroll
            for (int s = 0; s < 2; ++s) {
                uint32_t ah[4][4], al[4][4], bh[2][4], bl[2][4];
#pragma unroll
                for (int f = 0; f < 4; ++f) {
                    uint32_t aa = sA0 + c * A_CHUNK + (wm * 64 + f * 16 + arow) * A_STRIDE
                                + (s * 2 + ahalf) * 16;
                    ldsm4(aa,         ah[f][0], ah[f][1], ah[f][2], ah[f][3]);
                    ldsm4(aa + A_SEG, al[f][0], al[f][1], al[f][2], al[f][3]);
                }
#pragma unroll
                for (int g = 0; g < 2; ++g) {
                    uint32_t ba = sB0 + c * B_CHUNK + (s * 16 + blrow) * B_STRIDE
                                + (wn * 32 + g * 16 + bnc) * 2;
                    ldsm4t(ba,         bh[g][0], bh[g][1], bh[g][2], bh[g][3]);
                    ldsm4t(ba + B_SEG, bl[g][0], bl[g][1], bl[g][2], bl[g][3]);
                }
#pragma unroll
                for (int f = 0; f < 4; ++f) {
#pragma unroll
                    for (int g = 0; g < 2; ++g) {
                        mma16816(acc[f][g*2+0][0], acc[f][g*2+0][1], acc[f][g*2+0][2], acc[f][g*2+0][3],
                                 ah[f][0], ah[f][1], ah[f][2], ah[f][3], bh[g][0], bh[g][1]);
                        mma16816(acc[f][g*2+1][0], acc[f][g*2+1][1], acc[f][g*2+1][2], acc[f][g*2+1][3],
                                 ah[f][0], ah[f][1], ah[f][2], ah[f][3], bh[g][2], bh[g][3]);
                        mma16816(acc[f][g*2+0][0], acc[f][g*2+0][1], acc[f][g*2+0][2], acc[f][g*2+0][3],
                                 ah[f][0], ah[f][1], ah[f][2], ah[f][3], bl[g][0], bl[g][1]);
                        mma16816(acc[f][g*2+1][0], acc[f][g*2+1][1], acc[f][g*2+1][2], acc[f][g*2+1][3],
                                 ah[f][0], ah[f][1], ah[f][2], ah[f][3], bl[g][2], bl[g][3]);
                        mma16816(acc[f][g*2+0][0], acc[f][g*2+0][1], acc[f][g*2+0][2], acc[f][g*2+0][3],
                                 al[f][0], al[f][1], al[f][2], al[f][3], bh[g][0], bh[g][1]);
                        mma16816(acc[f][g*2+1][0], acc[f][g*2+1][1], acc[f][g*2+1][2], acc[f][g*2+1][3],
                                 al[f][0], al[f][1], al[f][2], al[f][3], bh[g][2], bh[g][3]);
                    }
                }
            }
        }
    };

    mma_pass();
    __syncthreads();

    loadB(M2hi, M2lo);
    cp_commit();

#pragma unroll
    for (int f = 0; f < 4; ++f) {
        int r0l = wm * 64 + f * 16 + tr;
        int r1l = r0l + 8;
#pragma unroll
        for (int g = 0; g < 4; ++g) {
            int col = wn * 32 + g * 8 + tc;
            float bb0 = m1_b[col], bb1 = m1_b[col + 1];
            float v00 = fmaxf(acc[f][g][0] + bb0, 0.f);
            float v01 = fmaxf(acc[f][g][1] + bb1, 0.f);
            float v10 = fmaxf(acc[f][g][2] + bb0, 0.f);
            float v11 = fmaxf(acc[f][g][3] + bb1, 0.f);
            uint32_t off0 = (col >> 5) * A_CHUNK + r0l * A_STRIDE + (col & 31) * 2;
            uint32_t off1 = (col >> 5) * A_CHUNK + r1l * A_STRIDE + (col & 31) * 2;
            bf16 h00 = __float2bfloat16(v00), h01 = __float2bfloat16(v01);
            bf16 h10 = __float2bfloat16(v10), h11 = __float2bfloat16(v11);
            *(__nv_bfloat162*)(sm + 65536 + off0) = __nv_bfloat162(h00, h01);
            *(__nv_bfloat162*)(sm + 65536 + off1) = __nv_bfloat162(h10, h11);
            *(__nv_bfloat162*)(sm + 65536 + A_SEG + off0) = __nv_bfloat162(
                __float2bfloat16(v00 - __bfloat162float(h00)),
                __float2bfloat16(v01 - __bfloat162float(h01)));
            *(__nv_bfloat162*)(sm + 65536 + A_SEG + off1) = __nv_bfloat162(
                __float2bfloat16(v10 - __bfloat162float(h10)),
                __float2bfloat16(v11 - __bfloat162float(h11)));
            acc[f][g][0] = acc[f][g][1] = acc[f][g][2] = acc[f][g][3] = 0.f;
        }
    }
    cp_wait<0>();
    __syncthreads();

    mma_pass();

#pragma unroll
    for (int f = 0; f < 4; ++f) {
        int m0 = row0 + wm * 64 + f * 16 + tr;
        int m1 = m0 + 8;
#pragma unroll
        for (int g = 0; g < 4; ++g) {
            int col = wn * 32 + g * 8 + tc;
            float bb0 = m2_b[col], bb1 = m2_b[col + 1];
            if (m0 < n_rows)
                *(float2*)(out + (size_t)m0 * 128 + col) =
                    make_float2(acc[f][g][0] + bb0, acc[f][g][1] + bb1);
            if (m1 < n_rows)
                *(float2*)(out + (size_t)m1 * 128 + col) =
                    make_float2(acc[f][g][2] + bb0, acc[f][g][3] + bb1);
        }
    }
}

// ---------------- merged weight split ----------------
__global__ __launch_bounds__(256) void wsplit_kernel(
    const float4* __restrict__ Wrel, const float4* __restrict__ w1W,
    const float4* __restrict__ m1W,  const float4* __restrict__ m2W,
    __nv_bfloat162* __restrict__ Wchi, __nv_bfloat162* __restrict__ Wclo,
    __nv_bfloat162* __restrict__ m1hi, __nv_bfloat162* __restrict__ m1lo,
    __nv_bfloat162* __restrict__ m2hi, __nv_bfloat162* __restrict__ m2lo)
{
    int i = blockIdx.x * 256 + threadIdx.x;
    if (i >= 11 * 4096) return;
    const int mat = i >> 12, local = i & 4095;
    const float4* in;
    __nv_bfloat162 *hi, *lo;
    if (mat < 8)       { in = Wrel + i;    hi = Wchi + i * 2;                  lo = Wclo + i * 2; }
    else if (mat == 8) { in = w1W + local; hi = Wchi + (8 * 4096 + local) * 2; lo = Wclo + (8 * 4096 + local) * 2; }
    else if (mat == 9) { in = m1W + local; hi = m1hi + local * 2;              lo = m1lo + local * 2; }
    else               { in = m2W + local; hi = m2hi + local * 2;              lo = m2lo + local * 2; }
    float4 v = *in;
    bf16 hx = __float2bfloat16(v.x), hy = __float2bfloat16(v.y);
    bf16 hz = __float2bfloat16(v.z), hw = __float2bfloat16(v.w);
    hi[0] = __nv_bfloat162(hx, hy);
    hi[1] = __nv_bfloat162(hz, hw);
    lo[0] = __nv_bfloat162(__float2bfloat16(v.x - __bfloat162float(hx)),
                           __float2bfloat16(v.y - __bfloat162float(hy)));
    lo[1] = __nv_bfloat162(__float2bfloat16(v.z - __bfloat162float(hz)),
                           __float2bfloat16(v.w - __bfloat162float(hw)));
}

// ---------------- edge scatter: 4 edges per warp (MLP x4) ----------------
__global__ __launch_bounds__(256) void edge_scatter(
    const float* __restrict__ hall,
    const int* __restrict__ src, const int* __restrict__ dst,
    const int* __restrict__ etype, float* __restrict__ agg)
{
    const int w    = (blockIdx.x * 256 + threadIdx.x) >> 5;
    const int lane = threadIdx.x & 31;
    const int e0   = w * 4;
    if (e0 >= Ee) return;

    int s[4], d[4], t[4];
#pragma unroll
    for (int i = 0; i < 4; ++i) {
        s[i] = __ldg(src + e0 + i);
        d[i] = __ldg(dst + e0 + i);
        t[i] = __ldg(etype + e0 + i);
    }
    float4 v[4];
#pragma unroll
    for (int i = 0; i < 4; ++i)
        v[i] = ((const float4*)(hall + ((size_t)t[i] * Nn + s[i]) * 128))[lane];
#pragma unroll
    for (int i = 0; i < 4; ++i) {
        float* o = agg + (size_t)d[i] * 128 + lane * 4;
        asm volatile("red.global.add.v4.f32 [%0], {%1,%2,%3,%4};"
                     :: "l"(o), "f"(v[i].x), "f"(v[i].y), "f"(v[i].z), "f"(v[i].w) : "memory");
    }
}

// ---------------- launch ----------------
extern "C" void kernel_launch(void* const* d_in, const int* in_sizes, int n_in,
                              void* d_out, int out_size)
{
    const float* x     = (const float*)d_in[0];
    const int*   src   = (const int*)  d_in[1];
    const int*   dst   = (const int*)  d_in[2];
    const int*   etype = (const int*)  d_in[3];
    const float* W_rel = (const float*)d_in[4];
    const float* w1_W  = (const float*)d_in[5];
    const float* w1_b  = (const float*)d_in[6];
    const float* m1_W  = (const float*)d_in[7];
    const float* m1_b  = (const float*)d_in[8];
    const float* m2_W  = (const float*)d_in[9];
    const float* m2_b  = (const float*)d_in[10];
    float* out = (float*)d_out;

    float *hall, *b1;
    bf16 *Wchi, *Wclo, *m1hi, *m1lo, *m2hi, *m2lo;
    cudaGetSymbolAddress((void**)&hall, g_hall);
    cudaGetSymbolAddress((void**)&b1,   g_b1);
    cudaGetSymbolAddress((void**)&Wchi, g_Wchi);
    cudaGetSymbolAddress((void**)&Wclo, g_Wclo);
    cudaGetSymbolAddress((void**)&m1hi, g_m1hi);
    cudaGetSymbolAddress((void**)&m1lo, g_m1lo);
    cudaGetSymbolAddress((void**)&m2hi, g_m2hi);
    cudaGetSymbolAddress((void**)&m2lo, g_m2lo);

    cudaFuncSetAttribute(rgemm_fused, cudaFuncAttributeMaxDynamicSharedMemorySize, FUSED_SMEM);
    cudaFuncSetAttribute(mlp_fused,   cudaFuncAttributeMaxDynamicSharedMemorySize, MLP_SMEM);

    const int nTiles = (Nn + 127) / 128;  // 391

    wsplit_kernel<<<(11 * 4096 + 255) / 256, 256>>>(
        (const float4*)W_rel, (const float4*)w1_W,
        (const float4*)m1_W, (const float4*)m2_W,
        (__nv_bfloat162*)Wchi, (__nv_bfloat162*)Wclo,
        (__nv_bfloat162*)m1hi, (__nv_bfloat162*)m1lo,
        (__nv_bfloat162*)m2hi, (__nv_bfloat162*)m2lo);

    rgemm_fused<<<nTiles, 256, FUSED_SMEM>>>(x, Wchi, Wclo, w1_b, hall, b1, Nn);

    edge_scatter<<<Ee / 32, 256>>>(hall, src, dst, etype, b1);   // 4 edges/warp

    mlp_fused<<<nTiles, 256, MLP_SMEM>>>(b1, m1hi, m1lo, m2hi, m2lo,
                                         m1_b, m2_b, out, Nn);
}